// round 1
// baseline (speedup 1.0000x reference)
#include <cuda_runtime.h>
#include <math.h>
#include <stdint.h>

// ---------------------------------------------------------------------------
// BondPredictor: GNN with alternating edge/node residual MLPs + edge decoder.
// Sizes (fixed by the dataset): N=20000 nodes, E=200000 edges, G=1000 graphs,
// NT=16, ND=256, ED=128, L=2, NE=5, TIME_DIM=DIST_DIM=16, NUM_T=1000.
// All math in fp32.
// ---------------------------------------------------------------------------

#define N_MAX 20000
#define E_MAX 200000

// Scratch (allocation-free: __device__ globals)
__device__ float g_hn   [(size_t)N_MAX * 256];
__device__ float g_he   [(size_t)E_MAX * 128];
__device__ float g_hid_e[(size_t)E_MAX * 128];
__device__ float g_msg  [(size_t)E_MAX * 256];
__device__ float g_agg  [(size_t)N_MAX * 256];
__device__ float g_hid_n[(size_t)N_MAX * 256];
__device__ float g_dist [(size_t)E_MAX * 16];
__device__ float g_tn   [N_MAX];
__device__ float g_te   [E_MAX];

// ---------------------------------------------------------------------------
// Generic tiled SGEMM: C[M,N] (maybe +=) = op( A[gidx or id][K] @ B[K,N] + bias )
//   - A row stride = K (compact), optional row gather via gidx
//   - B row-major with stride N (lets us point at row-slices of concat weights)
//   - accum: add into existing C (used for split-K partials AND residuals)
//   - relu applied last
// Tile: 64x64, BK=16, 256 threads, 4x4 per-thread microtile, float4 smem IO.
// Requires: N % 64 == 0, K % 16 == 0 (true for all call sites: K in {128,256}).
// ---------------------------------------------------------------------------
#define BM 64
#define BN 64
#define BK 16

__global__ void gemm_kernel(const float* __restrict__ A,
                            const int*   __restrict__ gidx,
                            const float* __restrict__ B,
                            const float* __restrict__ bias,
                            float* __restrict__ C,
                            int M, int N, int K, int relu, int accum)
{
    __shared__ float As[BK][BM];
    __shared__ float Bs[BK][BN];

    const int tid = threadIdx.x;            // 256 threads
    const int bn0 = blockIdx.x * BN;
    const int bm0 = blockIdx.y * BM;
    const int tx  = tid & 15;
    const int ty  = tid >> 4;

    // A loader: each thread loads one float4 -> covers 64 rows x 16 k
    const int a_m = tid >> 2;
    const int a_k = (tid & 3) * 4;
    const float* Arow = nullptr;
    {
        int row = bm0 + a_m;
        if (row < M) {
            int r = gidx ? gidx[row] : row;
            Arow = A + (size_t)r * K;
        }
    }
    // B loader: each thread loads one float4 -> 16 k x 64 n
    const int b_k = tid >> 4;
    const int b_n = (tid & 15) * 4;

    float acc[4][4];
#pragma unroll
    for (int i = 0; i < 4; i++)
#pragma unroll
        for (int j = 0; j < 4; j++) acc[i][j] = 0.0f;

    for (int k0 = 0; k0 < K; k0 += BK) {
        float4 av = make_float4(0.f, 0.f, 0.f, 0.f);
        if (Arow) av = *(const float4*)(Arow + k0 + a_k);
        As[a_k + 0][a_m] = av.x;
        As[a_k + 1][a_m] = av.y;
        As[a_k + 2][a_m] = av.z;
        As[a_k + 3][a_m] = av.w;

        *(float4*)&Bs[b_k][b_n] =
            *(const float4*)(B + (size_t)(k0 + b_k) * N + (bn0 + b_n));
        __syncthreads();

#pragma unroll
        for (int k = 0; k < BK; k++) {
            float4 a4 = *(const float4*)&As[k][ty * 4];
            float4 b4 = *(const float4*)&Bs[k][tx * 4];
            float ar[4] = {a4.x, a4.y, a4.z, a4.w};
            float br[4] = {b4.x, b4.y, b4.z, b4.w};
#pragma unroll
            for (int i = 0; i < 4; i++)
#pragma unroll
                for (int j = 0; j < 4; j++)
                    acc[i][j] = fmaf(ar[i], br[j], acc[i][j]);
        }
        __syncthreads();
    }

#pragma unroll
    for (int i = 0; i < 4; i++) {
        int m = bm0 + ty * 4 + i;
        if (m >= M) continue;
#pragma unroll
        for (int j = 0; j < 4; j++) {
            int n = bn0 + tx * 4 + j;
            float v = acc[i][j];
            if (bias)  v += bias[n];
            float* cp = &C[(size_t)m * N + n];
            if (accum) v += *cp;
            if (relu)  v = fmaxf(v, 0.0f);
            *cp = v;
        }
    }
}

// ---------------------------------------------------------------------------
// Elementwise / small kernels
// ---------------------------------------------------------------------------

// h_n[:, :240] = h_node @ W_node_emb ; h_n[:, 240:] = gsmear(t, 1000, 16)
__global__ void init_node_kernel(const float* __restrict__ h_node,
                                 const int*   __restrict__ batch_node,
                                 const int*   __restrict__ t,
                                 const float* __restrict__ Wne,
                                 float* __restrict__ hn, float* __restrict__ tn_out)
{
    int row = blockIdx.x;
    int c = threadIdx.x;  // 256
    __shared__ float h[16];
    __shared__ float tn_s;
    if (c < 16) h[c] = h_node[row * 16 + c];
    if (c == 0) tn_s = (float)t[batch_node[row]];
    __syncthreads();
    float tn = tn_s;
    float v;
    if (c < 240) {
        v = 0.f;
#pragma unroll
        for (int k = 0; k < 16; k++) v = fmaf(h[k], Wne[k * 240 + c], v);
    } else {
        const float step = 1000.0f / 15.0f;
        float dx = tn - (float)(c - 240) * step;
        v = expf((-0.5f / (step * step)) * dx * dx);
    }
    hn[(size_t)row * 256 + c] = v;
    if (c == 0) tn_out[row] = tn;
}

// h_e[:, :112] = [h_node[src], h_node[dst]] @ W_edge_emb ; h_e[:,112:] = gsmear(te)
// also dist_emb and te
__global__ void init_edge_kernel(const float* __restrict__ h_node,
                                 const float* __restrict__ pos,
                                 const int*   __restrict__ ei,
                                 const int*   __restrict__ batch_edge,
                                 const int*   __restrict__ t,
                                 const float* __restrict__ Wee,
                                 float* __restrict__ he, float* __restrict__ dist,
                                 float* __restrict__ te_out, int E)
{
    int e = blockIdx.x;
    int c = threadIdx.x;  // 128
    __shared__ float h[32];
    __shared__ float sh[2];
    int s = ei[e], d = ei[E + e];
    if (c < 16)       h[c] = h_node[s * 16 + c];
    else if (c < 32)  h[c] = h_node[d * 16 + (c - 16)];
    if (c == 0) {
        sh[0] = (float)t[batch_edge[e]];
        float dx = pos[d * 3 + 0] - pos[s * 3 + 0];
        float dy = pos[d * 3 + 1] - pos[s * 3 + 1];
        float dz = pos[d * 3 + 2] - pos[s * 3 + 2];
        sh[1] = sqrtf(dx * dx + dy * dy + dz * dz);
    }
    __syncthreads();
    float te = sh[0], dd = sh[1];
    float v;
    if (c < 112) {
        v = 0.f;
#pragma unroll
        for (int k = 0; k < 32; k++) v = fmaf(h[k], Wee[k * 112 + c], v);
    } else {
        const float step = 1000.0f / 15.0f;
        float dx = te - (float)(c - 112) * step;
        v = expf((-0.5f / (step * step)) * dx * dx);
    }
    he[(size_t)e * 128 + c] = v;
    if (c < 16) {
        const float step = 10.0f / 15.0f;
        float dx = dd - (float)c * step;
        dist[(size_t)e * 16 + c] = expf((-0.5f / (step * step)) * dx * dx);
    }
    if (c == 0) te_out[e] = te;
}

// hidden_e += dist_emb @ We1[640:656] + (te/1000) * We1[656] ; relu
__global__ void edge_finish_kernel(const float* __restrict__ dist,
                                   const float* __restrict__ te,
                                   const float* __restrict__ Wtail,  // 17 x 128
                                   float* __restrict__ C)
{
    int e = blockIdx.x;
    int c = threadIdx.x;  // 128
    __shared__ float ds[16];
    if (c < 16) ds[c] = dist[(size_t)e * 16 + c];
    __syncthreads();
    float v = C[(size_t)e * 128 + c];
#pragma unroll
    for (int k = 0; k < 16; k++) v = fmaf(ds[k], Wtail[k * 128 + c], v);
    v = fmaf(te[e] * (1.0f / 1000.0f), Wtail[16 * 128 + c], v);
    C[(size_t)e * 128 + c] = fmaxf(v, 0.0f);
}

// hidden_n += (tn/1000) * Wn1[512] ; relu
__global__ void node_finish_kernel(const float* __restrict__ tn,
                                   const float* __restrict__ Wrow,  // 256
                                   float* __restrict__ C)
{
    int n = blockIdx.x;
    int c = threadIdx.x;  // 256
    float v = fmaf(tn[n] * (1.0f / 1000.0f), Wrow[c], C[(size_t)n * 256 + c]);
    C[(size_t)n * 256 + c] = fmaxf(v, 0.0f);
}

__global__ void zero_kernel(float* __restrict__ p, int n)
{
    int i = blockIdx.x * 256 + threadIdx.x;
    if (i < n) p[i] = 0.0f;
}

// agg[dst[e]] += msg[e]   (spread-address float atomics)
__global__ void scatter_add_kernel(const float* __restrict__ msg,
                                   const int* __restrict__ dst,
                                   float* __restrict__ agg, int E)
{
    size_t i = (size_t)blockIdx.x * 256 + threadIdx.x;
    if (i >= (size_t)E * 256) return;
    int e = (int)(i >> 8);
    int c = (int)(i & 255);
    atomicAdd(&agg[(size_t)dst[e] * 256 + c], msg[i]);
}

// sym[i] = h_e[i] + h_e[i + nh]   (over nh*128 elements)
__global__ void sym_kernel(const float* __restrict__ he, float* __restrict__ out, int nh)
{
    size_t i = (size_t)blockIdx.x * 256 + threadIdx.x;
    if (i >= (size_t)nh * 128) return;
    out[i] = he[i] + he[i + (size_t)nh * 128];
}

// pair[i,c] = h_n[src[i],c] + h_n[dst[i],c]   (over nh*256)
__global__ void pair_kernel(const float* __restrict__ hn, const int* __restrict__ ei,
                            float* __restrict__ out, int nh, int E)
{
    size_t i = (size_t)blockIdx.x * 256 + threadIdx.x;
    if (i >= (size_t)nh * 256) return;
    int e = (int)(i >> 8);
    int c = (int)(i & 255);
    int s = ei[e], d = ei[E + e];
    out[i] = hn[(size_t)s * 256 + c] + hn[(size_t)d * 256 + c];
}

// out = h @ Wd3 + bd3   (128 -> 5)
__global__ void final_kernel(const float* __restrict__ h,
                             const float* __restrict__ Wd3,
                             const float* __restrict__ bd3,
                             float* __restrict__ out)
{
    int i = blockIdx.x;
    int c = threadIdx.x;  // 128
    __shared__ float sh[128];
    __shared__ float w[128 * 5];
    sh[c] = h[(size_t)i * 128 + c];
    for (int j = c; j < 640; j += 128) w[j] = Wd3[j];
    __syncthreads();
    if (c < 5) {
        float v = bd3[c];
#pragma unroll 8
        for (int k = 0; k < 128; k++) v = fmaf(sh[k], w[k * 5 + c], v);
        out[i * 5 + c] = v;
    }
}

// ---------------------------------------------------------------------------
// Host side
// ---------------------------------------------------------------------------

static void launch_gemm(const float* A, const int* gidx, const float* B,
                        const float* bias, float* C,
                        int M, int N, int K, int relu, int accum)
{
    dim3 grid(N / BN, (M + BM - 1) / BM);
    gemm_kernel<<<grid, 256>>>(A, gidx, B, bias, C, M, N, K, relu, accum);
}

template <typename T>
static float* sym_addr(T& symbol)
{
    void* p = nullptr;
    cudaGetSymbolAddress(&p, symbol);
    return (float*)p;
}

extern "C" void kernel_launch(void* const* d_in, const int* in_sizes, int n_in,
                              void* d_out, int out_size)
{
    const float* h_node     = (const float*)d_in[0];
    const float* pos        = (const float*)d_in[1];
    const int*   batch_node = (const int*)  d_in[2];
    const int*   ei         = (const int*)  d_in[3];
    const int*   batch_edge = (const int*)  d_in[4];
    const int*   t          = (const int*)  d_in[5];
    const float* Wne = (const float*)d_in[6];
    const float* Wee = (const float*)d_in[7];
    const float* We1 = (const float*)d_in[8];
    const float* be1 = (const float*)d_in[9];
    const float* We2 = (const float*)d_in[10];
    const float* be2 = (const float*)d_in[11];
    const float* Wm  = (const float*)d_in[12];
    const float* bm  = (const float*)d_in[13];
    const float* Wn1 = (const float*)d_in[14];
    const float* bn1 = (const float*)d_in[15];
    const float* Wn2 = (const float*)d_in[16];
    const float* bn2 = (const float*)d_in[17];
    const float* Wd1 = (const float*)d_in[18];
    const float* bd1 = (const float*)d_in[19];
    const float* Wd2 = (const float*)d_in[20];
    const float* bd2 = (const float*)d_in[21];
    const float* Wd3 = (const float*)d_in[22];
    const float* bd3 = (const float*)d_in[23];

    const int N  = in_sizes[0] / 16;   // 20000
    const int E  = in_sizes[4];        // 200000
    const int nh = E / 2;              // 100000
    const int* src = ei;
    const int* dst = ei + E;

    float* hn    = sym_addr(g_hn);
    float* he    = sym_addr(g_he);
    float* hid_e = sym_addr(g_hid_e);
    float* msg   = sym_addr(g_msg);
    float* agg   = sym_addr(g_agg);
    float* hid_n = sym_addr(g_hid_n);
    float* dist  = sym_addr(g_dist);
    float* tn    = sym_addr(g_tn);
    float* te    = sym_addr(g_te);

    // --- embeddings / geometric features ---
    init_node_kernel<<<N, 256>>>(h_node, batch_node, t, Wne, hn, tn);
    init_edge_kernel<<<E, 128>>>(h_node, pos, ei, batch_edge, t, Wee, he, dist, te, E);

    // --- L = 2 NodeEdgeNet blocks ---
    for (int l = 0; l < 2; l++) {
        const float* We1l = We1 + (size_t)l * 657 * 128;
        const float* be1l = be1 + (size_t)l * 128;
        const float* We2l = We2 + (size_t)l * 128 * 128;
        const float* be2l = be2 + (size_t)l * 128;
        const float* Wml  = Wm  + (size_t)l * 384 * 256;
        const float* bml  = bm  + (size_t)l * 256;
        const float* Wn1l = Wn1 + (size_t)l * 513 * 256;
        const float* bn1l = bn1 + (size_t)l * 256;
        const float* Wn2l = Wn2 + (size_t)l * 256 * 256;
        const float* bn2l = bn2 + (size_t)l * 256;

        // hidden_e = relu( [h_e, hn[src], hn[dst], dist, te] @ We1 + be1 )  (split-K)
        launch_gemm(he, nullptr, We1l,             be1l,    hid_e, E, 128, 128, 0, 0);
        launch_gemm(hn, src,     We1l + 128 * 128, nullptr, hid_e, E, 128, 256, 0, 1);
        launch_gemm(hn, dst,     We1l + 384 * 128, nullptr, hid_e, E, 128, 256, 0, 1);
        edge_finish_kernel<<<E, 128>>>(dist, te, We1l + 640 * 128, hid_e);

        // h_e += hidden_e @ We2 + be2   (residual via accum: C already holds h_e)
        launch_gemm(hid_e, nullptr, We2l, be2l, he, E, 128, 128, 0, 1);

        // msg = relu( [hn[src], h_e] @ Wm + bm )
        launch_gemm(hn, src,     Wml,             bml,     msg, E, 256, 256, 0, 0);
        launch_gemm(he, nullptr, Wml + 256 * 256, nullptr, msg, E, 256, 128, 1, 1);

        // agg = segment_sum(msg, dst)
        zero_kernel<<<(N * 256 + 255) / 256, 256>>>(agg, N * 256);
        scatter_add_kernel<<<(int)(((size_t)E * 256 + 255) / 256), 256>>>(msg, dst, agg, E);

        // hidden_n = relu( [h_n, agg, node_time] @ Wn1 + bn1 )
        launch_gemm(hn,  nullptr, Wn1l,             bn1l,    hid_n, N, 256, 256, 0, 0);
        launch_gemm(agg, nullptr, Wn1l + 256 * 256, nullptr, hid_n, N, 256, 256, 0, 1);
        node_finish_kernel<<<N, 256>>>(tn, Wn1l + 512 * 256, hid_n);

        // h_n += hidden_n @ Wn2 + bn2
        launch_gemm(hid_n, nullptr, Wn2l, bn2l, hn, N, 256, 256, 0, 1);
    }

    // --- decode ---
    // reuse: sym -> hid_e[0 : nh*128], dec1 -> hid_e[nh*128 : ], pair -> msg[0 : nh*256],
    //        dec2 -> msg[nh*256 : ]
    float* symb = hid_e;
    float* dec1 = hid_e + (size_t)nh * 128;
    float* pairb = msg;
    float* dec2 = msg + (size_t)nh * 256;

    sym_kernel <<<(int)(((size_t)nh * 128 + 255) / 256), 256>>>(he, symb, nh);
    pair_kernel<<<(int)(((size_t)nh * 256 + 255) / 256), 256>>>(hn, ei, pairb, nh, E);

    launch_gemm(symb,  nullptr, Wd1,             bd1,     dec1, nh, 128, 128, 0, 0);
    launch_gemm(pairb, nullptr, Wd1 + 128 * 128, nullptr, dec1, nh, 128, 256, 1, 1);
    launch_gemm(dec1,  nullptr, Wd2,             bd2,     dec2, nh, 128, 128, 1, 0);

    final_kernel<<<nh, 128>>>(dec2, Wd3, bd3, (float*)d_out);
}

// round 3
// speedup vs baseline: 1.2053x; 1.2053x over previous
#include <cuda_runtime.h>
#include <math.h>
#include <stdint.h>

// ---------------------------------------------------------------------------
// BondPredictor: GNN with alternating edge/node residual MLPs + edge decoder.
// N=20000 nodes, E=200000 edges, G=1000 graphs, ND=256, ED=128, L=2, NE=5.
// All math fp32; GEMM inner loop uses packed f32x2 FFMA2 (sm_100+).
// ---------------------------------------------------------------------------

#define N_MAX 20000
#define E_MAX 200000

__device__ float g_hn   [(size_t)N_MAX * 256];
__device__ float g_he   [(size_t)E_MAX * 128];
__device__ float g_hid_e[(size_t)E_MAX * 128];
__device__ float g_msg  [(size_t)E_MAX * 256];
__device__ float g_agg  [(size_t)N_MAX * 256];
__device__ float g_hid_n[(size_t)N_MAX * 256];
__device__ float g_dist [(size_t)E_MAX * 16];
__device__ float g_tn   [N_MAX];
__device__ float g_te   [E_MAX];

// ---------------------------------------------------------------------------
// Packed f32x2 helpers
// ---------------------------------------------------------------------------
__device__ __forceinline__ unsigned long long f32x2_dup(float x) {
    unsigned long long r;
    asm("mov.b64 %0, {%1, %1};" : "=l"(r) : "f"(x));
    return r;
}
__device__ __forceinline__ unsigned long long f32x2_fma(unsigned long long a,
                                                        unsigned long long b,
                                                        unsigned long long c) {
    unsigned long long d;
    asm("fma.rn.f32x2 %0, %1, %2, %3;" : "=l"(d) : "l"(a), "l"(b), "l"(c));
    return d;
}
__device__ __forceinline__ void f32x2_unpack(unsigned long long v, float& lo, float& hi) {
    asm("mov.b64 {%0, %1}, %2;" : "=f"(lo), "=f"(hi) : "l"(v));
}

// ---------------------------------------------------------------------------
// SGEMM v2: C[M,N] (opt +=) = op( A[gidx?][K] @ B[K,N] + bias )
// 128x128 tile, BK=16, 256 threads, 8x8 microtile, FFMA2 inner product.
// Requires N % 128 == 0, K % 16 == 0 (true: N in {128,256}, K in {128,256}).
// ---------------------------------------------------------------------------
#define BM 128
#define BN 128
#define BK 16

__global__ __launch_bounds__(256, 2)
void gemm_kernel(const float* __restrict__ A,
                 const int*   __restrict__ gidx,
                 const float* __restrict__ B,
                 const float* __restrict__ bias,
                 float* __restrict__ C,
                 int M, int N, int K, int relu, int accum)
{
    __shared__ __align__(16) float As[BK][BM];
    __shared__ __align__(16) float Bs[BK][BN];

    const int tid = threadIdx.x;
    const int bn0 = blockIdx.x * BN;
    const int bm0 = blockIdx.y * BM;

    // loader lanes
    const int lm  = tid >> 2;          // 0..63  (A row within half)
    const int lk  = (tid & 3) * 4;     // 0,4,8,12
    const int lbk = tid >> 4;          // 0..15  (B k)
    const int lbn = (tid & 15) * 4;    // 0..60  (B n within half)

    // compute lanes
    const int tx = tid & 15;           // n group of 8
    const int ty = tid >> 4;           // m group of 8

    // A row pointers (clamped for tail / gather)
    const float* Arow[2];
#pragma unroll
    for (int h = 0; h < 2; h++) {
        int row = bm0 + lm + 64 * h;
        int r = 0;
        if (row < M) r = gidx ? gidx[row] : row;
        Arow[h] = A + (size_t)r * K + lk;
    }

    unsigned long long acc[4][8];
#pragma unroll
    for (int i = 0; i < 4; i++)
#pragma unroll
        for (int j = 0; j < 8; j++) acc[i][j] = 0ull;

    // prefetch tile 0
    float4 a_reg[2], b_reg[2];
#pragma unroll
    for (int h = 0; h < 2; h++) {
        a_reg[h] = *(const float4*)(Arow[h]);
        b_reg[h] = *(const float4*)(B + (size_t)lbk * N + bn0 + lbn + 64 * h);
    }

    for (int k0 = 0; k0 < K; k0 += BK) {
        // store staged tile to smem
#pragma unroll
        for (int h = 0; h < 2; h++) {
            As[lk + 0][lm + 64 * h] = a_reg[h].x;
            As[lk + 1][lm + 64 * h] = a_reg[h].y;
            As[lk + 2][lm + 64 * h] = a_reg[h].z;
            As[lk + 3][lm + 64 * h] = a_reg[h].w;
            *(float4*)&Bs[lbk][lbn + 64 * h] = b_reg[h];
        }
        __syncthreads();

        // prefetch next tile
        if (k0 + BK < K) {
#pragma unroll
            for (int h = 0; h < 2; h++) {
                a_reg[h] = *(const float4*)(Arow[h] + k0 + BK);
                b_reg[h] = *(const float4*)(B + (size_t)(k0 + BK + lbk) * N + bn0 + lbn + 64 * h);
            }
        }

#pragma unroll
        for (int k = 0; k < BK; k++) {
            // A pairs read directly as packed f32x2 (m, m+1 contiguous)
            ulonglong2 a01 = *(const ulonglong2*)&As[k][ty * 8];
            ulonglong2 a23 = *(const ulonglong2*)&As[k][ty * 8 + 4];
            unsigned long long ap[4] = {a01.x, a01.y, a23.x, a23.y};

            float4 b0 = *(const float4*)&Bs[k][tx * 8];
            float4 b1 = *(const float4*)&Bs[k][tx * 8 + 4];
            unsigned long long bb[8];
            bb[0] = f32x2_dup(b0.x); bb[1] = f32x2_dup(b0.y);
            bb[2] = f32x2_dup(b0.z); bb[3] = f32x2_dup(b0.w);
            bb[4] = f32x2_dup(b1.x); bb[5] = f32x2_dup(b1.y);
            bb[6] = f32x2_dup(b1.z); bb[7] = f32x2_dup(b1.w);

#pragma unroll
            for (int ip = 0; ip < 4; ip++)
#pragma unroll
                for (int j = 0; j < 8; j++)
                    acc[ip][j] = f32x2_fma(ap[ip], bb[j], acc[ip][j]);
        }
        __syncthreads();
    }

    // epilogue: acc[ip][j] holds rows (m0+ip*2, m0+ip*2+1), col j
#pragma unroll
    for (int ip = 0; ip < 4; ip++) {
#pragma unroll
        for (int h = 0; h < 2; h++) {
            int m = bm0 + ty * 8 + ip * 2 + h;
            if (m >= M) continue;
            float v[8];
#pragma unroll
            for (int j = 0; j < 8; j++) {
                float lo, hi;
                f32x2_unpack(acc[ip][j], lo, hi);
                v[j] = h ? hi : lo;
            }
            float* cp = &C[(size_t)m * N + bn0 + tx * 8];
#pragma unroll
            for (int q = 0; q < 2; q++) {
                float4 cv = make_float4(v[q*4+0], v[q*4+1], v[q*4+2], v[q*4+3]);
                if (bias) {
                    const float4 bv = *(const float4*)&bias[bn0 + tx * 8 + q * 4];
                    cv.x += bv.x; cv.y += bv.y; cv.z += bv.z; cv.w += bv.w;
                }
                if (accum) {
                    float4 ov = *(const float4*)(cp + q * 4);
                    cv.x += ov.x; cv.y += ov.y; cv.z += ov.z; cv.w += ov.w;
                }
                if (relu) {
                    cv.x = fmaxf(cv.x, 0.f); cv.y = fmaxf(cv.y, 0.f);
                    cv.z = fmaxf(cv.z, 0.f); cv.w = fmaxf(cv.w, 0.f);
                }
                *(float4*)(cp + q * 4) = cv;
            }
        }
    }
}

// ---------------------------------------------------------------------------
// Elementwise / small kernels (unchanged where proven)
// ---------------------------------------------------------------------------

__global__ void init_node_kernel(const float* __restrict__ h_node,
                                 const int*   __restrict__ batch_node,
                                 const int*   __restrict__ t,
                                 const float* __restrict__ Wne,
                                 float* __restrict__ hn, float* __restrict__ tn_out)
{
    int row = blockIdx.x;
    int c = threadIdx.x;  // 256
    __shared__ float h[16];
    __shared__ float tn_s;
    if (c < 16) h[c] = h_node[row * 16 + c];
    if (c == 0) tn_s = (float)t[batch_node[row]];
    __syncthreads();
    float tn = tn_s;
    float v;
    if (c < 240) {
        v = 0.f;
#pragma unroll
        for (int k = 0; k < 16; k++) v = fmaf(h[k], Wne[k * 240 + c], v);
    } else {
        const float step = 1000.0f / 15.0f;
        float dx = tn - (float)(c - 240) * step;
        v = expf((-0.5f / (step * step)) * dx * dx);
    }
    hn[(size_t)row * 256 + c] = v;
    if (c == 0) tn_out[row] = tn;
}

__global__ void init_edge_kernel(const float* __restrict__ h_node,
                                 const float* __restrict__ pos,
                                 const int*   __restrict__ ei,
                                 const int*   __restrict__ batch_edge,
                                 const int*   __restrict__ t,
                                 const float* __restrict__ Wee,
                                 float* __restrict__ he, float* __restrict__ dist,
                                 float* __restrict__ te_out, int E)
{
    int e = blockIdx.x;
    int c = threadIdx.x;  // 128
    __shared__ float h[32];
    __shared__ float sh[2];
    int s = ei[e], d = ei[E + e];
    if (c < 16)       h[c] = h_node[s * 16 + c];
    else if (c < 32)  h[c] = h_node[d * 16 + (c - 16)];
    if (c == 0) {
        sh[0] = (float)t[batch_edge[e]];
        float dx = pos[d * 3 + 0] - pos[s * 3 + 0];
        float dy = pos[d * 3 + 1] - pos[s * 3 + 1];
        float dz = pos[d * 3 + 2] - pos[s * 3 + 2];
        sh[1] = sqrtf(dx * dx + dy * dy + dz * dz);
    }
    __syncthreads();
    float te = sh[0], dd = sh[1];
    float v;
    if (c < 112) {
        v = 0.f;
#pragma unroll
        for (int k = 0; k < 32; k++) v = fmaf(h[k], Wee[k * 112 + c], v);
    } else {
        const float step = 1000.0f / 15.0f;
        float dx = te - (float)(c - 112) * step;
        v = expf((-0.5f / (step * step)) * dx * dx);
    }
    he[(size_t)e * 128 + c] = v;
    if (c < 16) {
        const float step = 10.0f / 15.0f;
        float dx = dd - (float)c * step;
        dist[(size_t)e * 16 + c] = expf((-0.5f / (step * step)) * dx * dx);
    }
    if (c == 0) te_out[e] = te;
}

__global__ void edge_finish_kernel(const float* __restrict__ dist,
                                   const float* __restrict__ te,
                                   const float* __restrict__ Wtail,  // 17 x 128
                                   float* __restrict__ C)
{
    int e = blockIdx.x;
    int c = threadIdx.x;  // 128
    __shared__ float ds[16];
    if (c < 16) ds[c] = dist[(size_t)e * 16 + c];
    __syncthreads();
    float v = C[(size_t)e * 128 + c];
#pragma unroll
    for (int k = 0; k < 16; k++) v = fmaf(ds[k], Wtail[k * 128 + c], v);
    v = fmaf(te[e] * (1.0f / 1000.0f), Wtail[16 * 128 + c], v);
    C[(size_t)e * 128 + c] = fmaxf(v, 0.0f);
}

__global__ void node_finish_kernel(const float* __restrict__ tn,
                                   const float* __restrict__ Wrow,  // 256
                                   float* __restrict__ C)
{
    int n = blockIdx.x;
    int c = threadIdx.x;  // 256
    float v = fmaf(tn[n] * (1.0f / 1000.0f), Wrow[c], C[(size_t)n * 256 + c]);
    C[(size_t)n * 256 + c] = fmaxf(v, 0.0f);
}

__global__ void zero_kernel(float* __restrict__ p, int n)
{
    int i = blockIdx.x * 256 + threadIdx.x;
    if (i < n) p[i] = 0.0f;
}

// agg[dst[e]] += msg[e] — vectorized load, 4 scalar reductions per thread
__global__ void scatter_add_kernel(const float* __restrict__ msg,
                                   const int* __restrict__ dst,
                                   float* __restrict__ agg, int E)
{
    size_t i = (size_t)blockIdx.x * 256 + threadIdx.x;   // over E*64
    if (i >= (size_t)E * 64) return;
    int e = (int)(i >> 6);
    int c = (int)((i & 63) * 4);
    float4 mv = *(const float4*)&msg[(size_t)e * 256 + c];
    float* ap = &agg[(size_t)dst[e] * 256 + c];
    atomicAdd(ap + 0, mv.x);
    atomicAdd(ap + 1, mv.y);
    atomicAdd(ap + 2, mv.z);
    atomicAdd(ap + 3, mv.w);
}

__global__ void sym_kernel(const float* __restrict__ he, float* __restrict__ out, int nh)
{
    size_t i = (size_t)blockIdx.x * 256 + threadIdx.x;
    if (i >= (size_t)nh * 128) return;
    out[i] = he[i] + he[i + (size_t)nh * 128];
}

__global__ void pair_kernel(const float* __restrict__ hn, const int* __restrict__ ei,
                            float* __restrict__ out, int nh, int E)
{
    size_t i = (size_t)blockIdx.x * 256 + threadIdx.x;
    if (i >= (size_t)nh * 256) return;
    int e = (int)(i >> 8);
    int c = (int)(i & 255);
    int s = ei[e], d = ei[E + e];
    out[i] = hn[(size_t)s * 256 + c] + hn[(size_t)d * 256 + c];
}

__global__ void final_kernel(const float* __restrict__ h,
                             const float* __restrict__ Wd3,
                             const float* __restrict__ bd3,
                             float* __restrict__ out)
{
    int i = blockIdx.x;
    int c = threadIdx.x;  // 128
    __shared__ float sh[128];
    __shared__ float w[128 * 5];
    sh[c] = h[(size_t)i * 128 + c];
    for (int j = c; j < 640; j += 128) w[j] = Wd3[j];
    __syncthreads();
    if (c < 5) {
        float v = bd3[c];
#pragma unroll 8
        for (int k = 0; k < 128; k++) v = fmaf(sh[k], w[k * 5 + c], v);
        out[i * 5 + c] = v;
    }
}

// ---------------------------------------------------------------------------
// Host side
// ---------------------------------------------------------------------------

static void launch_gemm(const float* A, const int* gidx, const float* B,
                        const float* bias, float* C,
                        int M, int N, int K, int relu, int accum)
{
    dim3 grid(N / BN, (M + BM - 1) / BM);
    gemm_kernel<<<grid, 256>>>(A, gidx, B, bias, C, M, N, K, relu, accum);
}

template <typename T>
static float* sym_addr(T& symbol)
{
    void* p = nullptr;
    cudaGetSymbolAddress(&p, symbol);
    return (float*)p;
}

extern "C" void kernel_launch(void* const* d_in, const int* in_sizes, int n_in,
                              void* d_out, int out_size)
{
    const float* h_node     = (const float*)d_in[0];
    const float* pos        = (const float*)d_in[1];
    const int*   batch_node = (const int*)  d_in[2];
    const int*   ei         = (const int*)  d_in[3];
    const int*   batch_edge = (const int*)  d_in[4];
    const int*   t          = (const int*)  d_in[5];
    const float* Wne = (const float*)d_in[6];
    const float* Wee = (const float*)d_in[7];
    const float* We1 = (const float*)d_in[8];
    const float* be1 = (const float*)d_in[9];
    const float* We2 = (const float*)d_in[10];
    const float* be2 = (const float*)d_in[11];
    const float* Wm  = (const float*)d_in[12];
    const float* bm  = (const float*)d_in[13];
    const float* Wn1 = (const float*)d_in[14];
    const float* bn1 = (const float*)d_in[15];
    const float* Wn2 = (const float*)d_in[16];
    const float* bn2 = (const float*)d_in[17];
    const float* Wd1 = (const float*)d_in[18];
    const float* bd1 = (const float*)d_in[19];
    const float* Wd2 = (const float*)d_in[20];
    const float* bd2 = (const float*)d_in[21];
    const float* Wd3 = (const float*)d_in[22];
    const float* bd3 = (const float*)d_in[23];

    const int N  = in_sizes[0] / 16;   // 20000
    const int E  = in_sizes[4];        // 200000
    const int nh = E / 2;              // 100000
    const int* src = ei;
    const int* dst = ei + E;

    float* hn    = sym_addr(g_hn);
    float* he    = sym_addr(g_he);
    float* hid_e = sym_addr(g_hid_e);
    float* msg   = sym_addr(g_msg);
    float* agg   = sym_addr(g_agg);
    float* hid_n = sym_addr(g_hid_n);
    float* dist  = sym_addr(g_dist);
    float* tn    = sym_addr(g_tn);
    float* te    = sym_addr(g_te);

    // --- embeddings / geometric features ---
    init_node_kernel<<<N, 256>>>(h_node, batch_node, t, Wne, hn, tn);
    init_edge_kernel<<<E, 128>>>(h_node, pos, ei, batch_edge, t, Wee, he, dist, te, E);

    // --- L = 2 NodeEdgeNet blocks ---
    for (int l = 0; l < 2; l++) {
        const float* We1l = We1 + (size_t)l * 657 * 128;
        const float* be1l = be1 + (size_t)l * 128;
        const float* We2l = We2 + (size_t)l * 128 * 128;
        const float* be2l = be2 + (size_t)l * 128;
        const float* Wml  = Wm  + (size_t)l * 384 * 256;
        const float* bml  = bm  + (size_t)l * 256;
        const float* Wn1l = Wn1 + (size_t)l * 513 * 256;
        const float* bn1l = bn1 + (size_t)l * 256;
        const float* Wn2l = Wn2 + (size_t)l * 256 * 256;
        const float* bn2l = bn2 + (size_t)l * 256;

        // hidden_e = relu( [h_e, hn[src], hn[dst], dist, te] @ We1 + be1 )  (split-K)
        launch_gemm(he, nullptr, We1l,             be1l,    hid_e, E, 128, 128, 0, 0);
        launch_gemm(hn, src,     We1l + 128 * 128, nullptr, hid_e, E, 128, 256, 0, 1);
        launch_gemm(hn, dst,     We1l + 384 * 128, nullptr, hid_e, E, 128, 256, 0, 1);
        edge_finish_kernel<<<E, 128>>>(dist, te, We1l + 640 * 128, hid_e);

        // h_e += hidden_e @ We2 + be2
        launch_gemm(hid_e, nullptr, We2l, be2l, he, E, 128, 128, 0, 1);

        // msg = relu( [hn[src], h_e] @ Wm + bm )
        launch_gemm(hn, src,     Wml,             bml,     msg, E, 256, 256, 0, 0);
        launch_gemm(he, nullptr, Wml + 256 * 256, nullptr, msg, E, 256, 128, 1, 1);

        // agg = segment_sum(msg, dst)
        zero_kernel<<<(N * 256 + 255) / 256, 256>>>(agg, N * 256);
        scatter_add_kernel<<<(int)(((size_t)E * 64 + 255) / 256), 256>>>(msg, dst, agg, E);

        // hidden_n = relu( [h_n, agg, node_time] @ Wn1 + bn1 )
        launch_gemm(hn,  nullptr, Wn1l,             bn1l,    hid_n, N, 256, 256, 0, 0);
        launch_gemm(agg, nullptr, Wn1l + 256 * 256, nullptr, hid_n, N, 256, 256, 0, 1);
        node_finish_kernel<<<N, 256>>>(tn, Wn1l + 512 * 256, hid_n);

        // h_n += hidden_n @ Wn2 + bn2
        launch_gemm(hid_n, nullptr, Wn2l, bn2l, hn, N, 256, 256, 0, 1);
    }

    // --- decode ---
    float* symb  = hid_e;
    float* dec1  = hid_e + (size_t)nh * 128;
    float* pairb = msg;
    float* dec2  = msg + (size_t)nh * 256;

    sym_kernel <<<(int)(((size_t)nh * 128 + 255) / 256), 256>>>(he, symb, nh);
    pair_kernel<<<(int)(((size_t)nh * 256 + 255) / 256), 256>>>(hn, ei, pairb, nh, E);

    launch_gemm(symb,  nullptr, Wd1,             bd1,     dec1, nh, 128, 128, 0, 0);
    launch_gemm(pairb, nullptr, Wd1 + 128 * 128, nullptr, dec1, nh, 128, 256, 1, 1);
    launch_gemm(dec1,  nullptr, Wd2,             bd2,     dec2, nh, 128, 128, 1, 0);

    final_kernel<<<nh, 128>>>(dec2, Wd3, bd3, (float*)d_out);
}

// round 5
// speedup vs baseline: 1.4976x; 1.2425x over previous
#include <cuda_runtime.h>
#include <cuda_bf16.h>
#include <math.h>
#include <stdint.h>

// ===========================================================================
// BondPredictor: all GEMMs on HMMA tensor cores (mma.sync bf16) via bf16x3
// split precision (x = hi + lo; x*y ~= hi*hi + hi*lo + lo*hi).
// N=20000 nodes, E=200000 edges, ND=256, ED=128, L=2, NE=5.
// ===========================================================================

#define N_MAX 20000
#define E_MAX 200000
#define NH_MAX (E_MAX / 2)

// ------------------------- fp32 scratch -----------------------------------
__device__ float g_hn   [(size_t)N_MAX * 256];
__device__ float g_he   [(size_t)E_MAX * 128];
__device__ float g_hid_e[(size_t)E_MAX * 128];
__device__ float g_msg  [(size_t)E_MAX * 256];
__device__ float g_agg  [(size_t)N_MAX * 256];
__device__ float g_hid_n[(size_t)N_MAX * 256];
__device__ float g_dist [(size_t)E_MAX * 16];
__device__ float g_tn   [N_MAX];
__device__ float g_te   [E_MAX];

// ------------------------- bf16 hi/lo planes (activations) -----------------
__device__ __nv_bfloat16 g_hn_h  [(size_t)N_MAX * 256];
__device__ __nv_bfloat16 g_hn_l  [(size_t)N_MAX * 256];
__device__ __nv_bfloat16 g_he_h  [(size_t)E_MAX * 128];
__device__ __nv_bfloat16 g_he_l  [(size_t)E_MAX * 128];
__device__ __nv_bfloat16 g_hide_h[(size_t)E_MAX * 128];
__device__ __nv_bfloat16 g_hide_l[(size_t)E_MAX * 128];
__device__ __nv_bfloat16 g_agg_h [(size_t)N_MAX * 256];
__device__ __nv_bfloat16 g_agg_l [(size_t)N_MAX * 256];
__device__ __nv_bfloat16 g_hidn_h[(size_t)N_MAX * 256];
__device__ __nv_bfloat16 g_hidn_l[(size_t)N_MAX * 256];
__device__ __nv_bfloat16 g_sym_h [(size_t)NH_MAX * 128];
__device__ __nv_bfloat16 g_sym_l [(size_t)NH_MAX * 128];
__device__ __nv_bfloat16 g_pair_h[(size_t)NH_MAX * 256];
__device__ __nv_bfloat16 g_pair_l[(size_t)NH_MAX * 256];
__device__ __nv_bfloat16 g_dec1_h[(size_t)NH_MAX * 128];
__device__ __nv_bfloat16 g_dec1_l[(size_t)NH_MAX * 128];

// ------------------------- transposed+split weights [N, ldt] ---------------
__device__ __nv_bfloat16 g_We1t_h[2 * 128 * 664];
__device__ __nv_bfloat16 g_We1t_l[2 * 128 * 664];
__device__ __nv_bfloat16 g_We2t_h[2 * 128 * 128];
__device__ __nv_bfloat16 g_We2t_l[2 * 128 * 128];
__device__ __nv_bfloat16 g_Wmt_h [2 * 256 * 384];
__device__ __nv_bfloat16 g_Wmt_l [2 * 256 * 384];
__device__ __nv_bfloat16 g_Wn1t_h[2 * 256 * 520];
__device__ __nv_bfloat16 g_Wn1t_l[2 * 256 * 520];
__device__ __nv_bfloat16 g_Wn2t_h[2 * 256 * 256];
__device__ __nv_bfloat16 g_Wn2t_l[2 * 256 * 256];
__device__ __nv_bfloat16 g_Wd1t_h[128 * 384];
__device__ __nv_bfloat16 g_Wd1t_l[128 * 384];
__device__ __nv_bfloat16 g_Wd2t_h[128 * 128];
__device__ __nv_bfloat16 g_Wd2t_l[128 * 128];

// ===========================================================================
// PTX helpers (sm_80-era: valid on plain sm_103 target)
// ===========================================================================
__device__ __forceinline__ uint32_t smem_u32(const void* p) {
    uint32_t a;
    asm("{ .reg .u64 t; cvta.to.shared.u64 t, %1; cvt.u32.u64 %0, t; }"
        : "=r"(a) : "l"(p));
    return a;
}
__device__ __forceinline__ void cp16(uint32_t dst, const void* src) {
    asm volatile("cp.async.cg.shared.global [%0], [%1], 16;" :: "r"(dst), "l"(src));
}
#define CP_COMMIT()  asm volatile("cp.async.commit_group;" ::: "memory")
#define CP_WAIT(n)   asm volatile("cp.async.wait_group %0;" :: "n"(n) : "memory")

#define LDSM4(r0, r1, r2, r3, addr) \
    asm volatile("ldmatrix.sync.aligned.m8n8.x4.shared.b16 {%0,%1,%2,%3}, [%4];" \
                 : "=r"(r0), "=r"(r1), "=r"(r2), "=r"(r3) : "r"(addr))

#define MMA16816(d, a, b0, b1) \
    asm volatile("mma.sync.aligned.m16n8k16.row.col.f32.bf16.bf16.f32 " \
                 "{%0,%1,%2,%3},{%4,%5,%6,%7},{%8,%9},{%0,%1,%2,%3};" \
                 : "+f"((d)[0]), "+f"((d)[1]), "+f"((d)[2]), "+f"((d)[3]) \
                 : "r"((a)[0]), "r"((a)[1]), "r"((a)[2]), "r"((a)[3]), \
                   "r"(b0), "r"(b1))

__device__ __forceinline__ void bf16_split(float x, __nv_bfloat16& h, __nv_bfloat16& l) {
    h = __float2bfloat16(x);
    l = __float2bfloat16(x - __bfloat162float(h));
}

// ===========================================================================
// HMMA GEMM: C[M, Nfull] (opt +=) = op( A[gidx?][K] @ Bt^T + bias )
//   A: bf16 hi/lo planes [*, K]; Bt: transposed planes [Nfull, ldb].
//   bf16x3: chunks of 64 k-elems over K' = 3K; pass p = chunk*64/K selects
//   planes (A: hi,hi,lo ; B: hi,lo,hi). Requires K % 64 == 0.
//   Block 128x128, 8 warps as 4(m) x 2(n) -> warp tile 32x64.
//   BK=64 (128B rows, SW128 swizzle), cp.async double buffering.
// smem: A bufs 2x16KB @0, B bufs 2x16KB @32768 -> 64KB.
// ===========================================================================
#define TG_SMEM_BYTES 65536

__global__ __launch_bounds__(256)
void tgemm_kernel(const __nv_bfloat16* __restrict__ Ahi,
                  const __nv_bfloat16* __restrict__ Alo,
                  const int*           __restrict__ gidx,
                  const __nv_bfloat16* __restrict__ Bhi,   // [Nfull, ldb]
                  const __nv_bfloat16* __restrict__ Blo,
                  int ldb,
                  const float* __restrict__ bias,
                  float* __restrict__ C,
                  __nv_bfloat16* __restrict__ Chi,
                  __nv_bfloat16* __restrict__ Clo,
                  int M, int Nfull, int K, int relu, int accum)
{
    extern __shared__ char smem[];
    const uint32_t sbase = smem_u32(smem);
    const int tid = threadIdx.x;
    const int L   = tid & 31;
    const int wid = tid >> 5;
    const int wm  = wid >> 1;      // 0..3
    const int wn  = wid & 1;       // 0..1
    const int bn0 = blockIdx.x * 128;
    const int bm0 = blockIdx.y * 128;

    // ---- staging setup: thread -> (row srow 0..127, half sh 0..1) ----
    const int srow = tid >> 1;
    const int sh   = tid & 1;
    uint32_t soff[4];
#pragma unroll
    for (int i = 0; i < 4; i++) {
        int ch = sh * 4 + i;
        soff[i] = (uint32_t)(srow * 128 + ((ch ^ (srow & 7)) * 16));
    }
    int arow_g = bm0 + srow;
    int gr = 0;
    if (arow_g < M) gr = gidx ? gidx[arow_g] : arow_g;
    const __nv_bfloat16* aph = Ahi + (size_t)gr * K + sh * 32;
    const __nv_bfloat16* apl = Alo + (size_t)gr * K + sh * 32;
    const __nv_bfloat16* bph = Bhi + (size_t)(bn0 + srow) * ldb + sh * 32;
    const __nv_bfloat16* bpl = Blo + (size_t)(bn0 + srow) * ldb + sh * 32;

    const int nch = 3 * K / 64;

    // ---- ldmatrix per-lane address precompute ----
    // A frag (mf): rows mf*16 + ((L>>3)&1)*8 + (L&7); chunk = 2j + (L>>4)
    // B frag pair (nf2): rows nf2*16 + (L>>4)*8 + (L&7); chunk = 2j + ((L>>3)&1)
    uint32_t a_rbase[2], b_rbase[4];
    int a_rsw[2], b_rsw[4];
    const int a_csel = L >> 4;
    const int b_csel = (L >> 3) & 1;
#pragma unroll
    for (int mf = 0; mf < 2; mf++) {
        int r = wm * 32 + mf * 16 + ((L >> 3) & 1) * 8 + (L & 7);
        a_rbase[mf] = (uint32_t)(r * 128);
        a_rsw[mf] = r & 7;
    }
#pragma unroll
    for (int nf2 = 0; nf2 < 4; nf2++) {
        int r = wn * 64 + nf2 * 16 + (L >> 4) * 8 + (L & 7);
        b_rbase[nf2] = (uint32_t)(r * 128);
        b_rsw[nf2] = r & 7;
    }

    float acc[2][8][4];
#pragma unroll
    for (int mf = 0; mf < 2; mf++)
#pragma unroll
        for (int nf = 0; nf < 8; nf++)
#pragma unroll
            for (int q = 0; q < 4; q++) acc[mf][nf][q] = 0.0f;

    // ---- stage chunk 0 ----
    {
        const __nv_bfloat16* as = aph;     // p=0: hi
        const __nv_bfloat16* bs = bph;
        uint32_t ab = sbase, bb = sbase + 32768;
#pragma unroll
        for (int i = 0; i < 4; i++) {
            cp16(ab + soff[i], as + i * 8);
            cp16(bb + soff[i], bs + i * 8);
        }
        CP_COMMIT();
    }

    for (int c = 0; c < nch; c++) {
        const int buf = c & 1;
        if (c + 1 < nch) {
            const int c1 = c + 1;
            const int p  = (c1 * 64) / K;
            const int k0 = (c1 * 64) % K;
            const __nv_bfloat16* as = ((p == 2) ? apl : aph) + k0;
            const __nv_bfloat16* bs = ((p == 1) ? bpl : bph) + k0;
            uint32_t ab = sbase + (c1 & 1) * 16384;
            uint32_t bb = sbase + 32768 + (c1 & 1) * 16384;
#pragma unroll
            for (int i = 0; i < 4; i++) {
                cp16(ab + soff[i], as + i * 8);
                cp16(bb + soff[i], bs + i * 8);
            }
            CP_COMMIT();
            CP_WAIT(1);
        } else {
            CP_WAIT(0);
        }
        __syncthreads();

        const uint32_t Ab = sbase + buf * 16384;
        const uint32_t Bb = sbase + 32768 + buf * 16384;
#pragma unroll
        for (int j = 0; j < 4; j++) {
            uint32_t a0[4], a1[4];
            {
                uint32_t ca = (uint32_t)(((2 * j + a_csel) ^ a_rsw[0]) * 16);
                LDSM4(a0[0], a0[1], a0[2], a0[3], Ab + a_rbase[0] + ca);
                uint32_t cb = (uint32_t)(((2 * j + a_csel) ^ a_rsw[1]) * 16);
                LDSM4(a1[0], a1[1], a1[2], a1[3], Ab + a_rbase[1] + cb);
            }
            uint32_t bv[4][4];
#pragma unroll
            for (int nf2 = 0; nf2 < 4; nf2++) {
                uint32_t cb = (uint32_t)(((2 * j + b_csel) ^ b_rsw[nf2]) * 16);
                LDSM4(bv[nf2][0], bv[nf2][1], bv[nf2][2], bv[nf2][3],
                      Bb + b_rbase[nf2] + cb);
            }
#pragma unroll
            for (int nf2 = 0; nf2 < 4; nf2++) {
                MMA16816(acc[0][2 * nf2],     a0, bv[nf2][0], bv[nf2][1]);
                MMA16816(acc[0][2 * nf2 + 1], a0, bv[nf2][2], bv[nf2][3]);
                MMA16816(acc[1][2 * nf2],     a1, bv[nf2][0], bv[nf2][1]);
                MMA16816(acc[1][2 * nf2 + 1], a1, bv[nf2][2], bv[nf2][3]);
            }
        }
        __syncthreads();
    }

    // ---- epilogue ----
    // d0,d1: (row = base + L/4, cols c,c+1); d2,d3: row+8
#pragma unroll
    for (int mf = 0; mf < 2; mf++) {
#pragma unroll
        for (int nf = 0; nf < 8; nf++) {
            const int col = bn0 + wn * 64 + nf * 8 + (L & 3) * 2;
#pragma unroll
            for (int half = 0; half < 2; half++) {
                const int m = bm0 + wm * 32 + mf * 16 + (L >> 2) + half * 8;
                if (m >= M) continue;
                float v0 = acc[mf][nf][half * 2 + 0];
                float v1 = acc[mf][nf][half * 2 + 1];
                if (bias) { v0 += bias[col]; v1 += bias[col + 1]; }
                float* cp = &C[(size_t)m * Nfull + col];
                if (accum) { v0 += cp[0]; v1 += cp[1]; }
                if (relu)  { v0 = fmaxf(v0, 0.f); v1 = fmaxf(v1, 0.f); }
                cp[0] = v0; cp[1] = v1;
                if (Chi) {
                    __nv_bfloat16 h0, l0, h1, l1;
                    bf16_split(v0, h0, l0);
                    bf16_split(v1, h1, l1);
                    size_t o = (size_t)m * Nfull + col;
                    Chi[o] = h0; Chi[o + 1] = h1;
                    Clo[o] = l0; Clo[o + 1] = l1;
                }
            }
        }
    }
}

// ===========================================================================
// Weight transpose + split: W[K,N] fp32 -> Th/Tl [N, ldt] bf16
// ===========================================================================
__global__ void wt_conv_kernel(const float* __restrict__ W, int K, int N,
                               __nv_bfloat16* __restrict__ Th,
                               __nv_bfloat16* __restrict__ Tl, int ldt)
{
    __shared__ float tile[32][33];
    const int k0 = blockIdx.y * 32, n0 = blockIdx.x * 32;
    const int tx = threadIdx.x, ty = threadIdx.y;  // 32x8
    for (int i = ty; i < 32; i += 8) {
        int k = k0 + i, n = n0 + tx;
        tile[i][tx] = (k < K && n < N) ? W[(size_t)k * N + n] : 0.0f;
    }
    __syncthreads();
    for (int i = ty; i < 32; i += 8) {
        int n = n0 + i, k = k0 + tx;
        if (n < N && k < ldt) {
            float x = tile[tx][i];
            __nv_bfloat16 hb, lb;
            bf16_split(x, hb, lb);
            Th[(size_t)n * ldt + k] = hb;
            Tl[(size_t)n * ldt + k] = lb;
        }
    }
}

__global__ void act_conv_kernel(const float* __restrict__ X,
                                __nv_bfloat16* __restrict__ Xh,
                                __nv_bfloat16* __restrict__ Xl, int n4)
{
    int i = blockIdx.x * 256 + threadIdx.x;
    if (i >= n4) return;
    float4 x = ((const float4*)X)[i];
    __nv_bfloat16 hh[4], ll[4];
    bf16_split(x.x, hh[0], ll[0]);
    bf16_split(x.y, hh[1], ll[1]);
    bf16_split(x.z, hh[2], ll[2]);
    bf16_split(x.w, hh[3], ll[3]);
    *(uint2*)(Xh + (size_t)i * 4) = *(uint2*)hh;
    *(uint2*)(Xl + (size_t)i * 4) = *(uint2*)ll;
}

// ===========================================================================
// Elementwise / small kernels (with plane epilogues)
// ===========================================================================
__global__ void init_node_kernel(const float* __restrict__ h_node,
                                 const int* __restrict__ batch_node,
                                 const int* __restrict__ t,
                                 const float* __restrict__ Wne,
                                 float* __restrict__ hn,
                                 __nv_bfloat16* __restrict__ hn_h,
                                 __nv_bfloat16* __restrict__ hn_l,
                                 float* __restrict__ tn_out)
{
    int row = blockIdx.x;
    int c = threadIdx.x;  // 256
    __shared__ float hsh[16];
    __shared__ float tn_s;
    if (c < 16) hsh[c] = h_node[row * 16 + c];
    if (c == 0) tn_s = (float)t[batch_node[row]];
    __syncthreads();
    float tn = tn_s;
    float v;
    if (c < 240) {
        v = 0.f;
#pragma unroll
        for (int k = 0; k < 16; k++) v = fmaf(hsh[k], Wne[k * 240 + c], v);
    } else {
        const float step = 1000.0f / 15.0f;
        float dx = tn - (float)(c - 240) * step;
        v = expf((-0.5f / (step * step)) * dx * dx);
    }
    size_t idx = (size_t)row * 256 + c;
    hn[idx] = v;
    __nv_bfloat16 hb, lb; bf16_split(v, hb, lb);
    hn_h[idx] = hb; hn_l[idx] = lb;
    if (c == 0) tn_out[row] = tn;
}

__global__ void init_edge_kernel(const float* __restrict__ h_node,
                                 const float* __restrict__ pos,
                                 const int* __restrict__ ei,
                                 const int* __restrict__ batch_edge,
                                 const int* __restrict__ t,
                                 const float* __restrict__ Wee,
                                 float* __restrict__ he,
                                 __nv_bfloat16* __restrict__ he_h,
                                 __nv_bfloat16* __restrict__ he_l,
                                 float* __restrict__ dist,
                                 float* __restrict__ te_out, int E)
{
    int e = blockIdx.x;
    int c = threadIdx.x;  // 128
    __shared__ float hsh[32];
    __shared__ float sh[2];
    int s = ei[e], d = ei[E + e];
    if (c < 16)      hsh[c] = h_node[s * 16 + c];
    else if (c < 32) hsh[c] = h_node[d * 16 + (c - 16)];
    if (c == 0) {
        sh[0] = (float)t[batch_edge[e]];
        float dx = pos[d * 3 + 0] - pos[s * 3 + 0];
        float dy = pos[d * 3 + 1] - pos[s * 3 + 1];
        float dz = pos[d * 3 + 2] - pos[s * 3 + 2];
        sh[1] = sqrtf(dx * dx + dy * dy + dz * dz);
    }
    __syncthreads();
    float te = sh[0], dd = sh[1];
    float v;
    if (c < 112) {
        v = 0.f;
#pragma unroll
        for (int k = 0; k < 32; k++) v = fmaf(hsh[k], Wee[k * 112 + c], v);
    } else {
        const float step = 1000.0f / 15.0f;
        float dx = te - (float)(c - 112) * step;
        v = expf((-0.5f / (step * step)) * dx * dx);
    }
    size_t idx = (size_t)e * 128 + c;
    he[idx] = v;
    __nv_bfloat16 hb, lb; bf16_split(v, hb, lb);
    he_h[idx] = hb; he_l[idx] = lb;
    if (c < 16) {
        const float step = 10.0f / 15.0f;
        float dx = dd - (float)c * step;
        dist[(size_t)e * 16 + c] = expf((-0.5f / (step * step)) * dx * dx);
    }
    if (c == 0) te_out[e] = te;
}

__global__ void edge_finish_kernel(const float* __restrict__ dist,
                                   const float* __restrict__ te,
                                   const float* __restrict__ Wtail,  // 17 x 128
                                   float* __restrict__ C,
                                   __nv_bfloat16* __restrict__ Ch,
                                   __nv_bfloat16* __restrict__ Cl)
{
    int e = blockIdx.x;
    int c = threadIdx.x;  // 128
    __shared__ float ds[16];
    if (c < 16) ds[c] = dist[(size_t)e * 16 + c];
    __syncthreads();
    size_t idx = (size_t)e * 128 + c;
    float v = C[idx];
#pragma unroll
    for (int k = 0; k < 16; k++) v = fmaf(ds[k], Wtail[k * 128 + c], v);
    v = fmaf(te[e] * (1.0f / 1000.0f), Wtail[16 * 128 + c], v);
    v = fmaxf(v, 0.0f);
    C[idx] = v;
    __nv_bfloat16 hb, lb; bf16_split(v, hb, lb);
    Ch[idx] = hb; Cl[idx] = lb;
}

__global__ void node_finish_kernel(const float* __restrict__ tn,
                                   const float* __restrict__ Wrow,  // 256
                                   float* __restrict__ C,
                                   __nv_bfloat16* __restrict__ Ch,
                                   __nv_bfloat16* __restrict__ Cl)
{
    int n = blockIdx.x;
    int c = threadIdx.x;  // 256
    size_t idx = (size_t)n * 256 + c;
    float v = fmaf(tn[n] * (1.0f / 1000.0f), Wrow[c], C[idx]);
    v = fmaxf(v, 0.0f);
    C[idx] = v;
    __nv_bfloat16 hb, lb; bf16_split(v, hb, lb);
    Ch[idx] = hb; Cl[idx] = lb;
}

__global__ void zero_kernel(float* __restrict__ p, int n)
{
    int i = blockIdx.x * 256 + threadIdx.x;
    if (i < n) p[i] = 0.0f;
}

__global__ void scatter_add_kernel(const float* __restrict__ msg,
                                   const int* __restrict__ dst,
                                   float* __restrict__ agg, int E)
{
    size_t i = (size_t)blockIdx.x * 256 + threadIdx.x;  // over E*64
    if (i >= (size_t)E * 64) return;
    int e = (int)(i >> 6);
    int c = (int)((i & 63) * 4);
    float4 mv = *(const float4*)&msg[(size_t)e * 256 + c];
    float* ap = &agg[(size_t)dst[e] * 256 + c];
    atomicAdd(ap + 0, mv.x);
    atomicAdd(ap + 1, mv.y);
    atomicAdd(ap + 2, mv.z);
    atomicAdd(ap + 3, mv.w);
}

__global__ void sym_kernel(const float* __restrict__ he,
                           __nv_bfloat16* __restrict__ oh,
                           __nv_bfloat16* __restrict__ ol, int nh)
{
    size_t i = (size_t)blockIdx.x * 256 + threadIdx.x;
    if (i >= (size_t)nh * 128) return;
    float v = he[i] + he[i + (size_t)nh * 128];
    __nv_bfloat16 hb, lb; bf16_split(v, hb, lb);
    oh[i] = hb; ol[i] = lb;
}

__global__ void pair_kernel(const float* __restrict__ hn, const int* __restrict__ ei,
                            __nv_bfloat16* __restrict__ oh,
                            __nv_bfloat16* __restrict__ ol, int nh, int E)
{
    size_t i = (size_t)blockIdx.x * 256 + threadIdx.x;
    if (i >= (size_t)nh * 256) return;
    int e = (int)(i >> 8);
    int c = (int)(i & 255);
    int s = ei[e], d = ei[E + e];
    float v = hn[(size_t)s * 256 + c] + hn[(size_t)d * 256 + c];
    __nv_bfloat16 hb, lb; bf16_split(v, hb, lb);
    oh[i] = hb; ol[i] = lb;
}

__global__ void final_kernel(const float* __restrict__ h,
                             const float* __restrict__ Wd3,
                             const float* __restrict__ bd3,
                             float* __restrict__ out)
{
    int i = blockIdx.x;
    int c = threadIdx.x;  // 128
    __shared__ float sh[128];
    __shared__ float w[128 * 5];
    sh[c] = h[(size_t)i * 128 + c];
    for (int j = c; j < 640; j += 128) w[j] = Wd3[j];
    __syncthreads();
    if (c < 5) {
        float v = bd3[c];
#pragma unroll 8
        for (int k = 0; k < 128; k++) v = fmaf(sh[k], w[k * 5 + c], v);
        out[i * 5 + c] = v;
    }
}

// ===========================================================================
// Host side
// ===========================================================================
template <typename T>
static T* sym_addr(T* symbol)
{
    void* p = nullptr;
    cudaGetSymbolAddress(&p, (const void*)symbol);
    return (T*)p;
}

static void launch_tgemm(const __nv_bfloat16* Ah, const __nv_bfloat16* Al,
                         const int* gidx,
                         const __nv_bfloat16* Bh, const __nv_bfloat16* Bl, int ldb,
                         const float* bias, float* C,
                         __nv_bfloat16* Ch, __nv_bfloat16* Cl,
                         int M, int Nfull, int K, int relu, int accum)
{
    dim3 grid(Nfull / 128, (M + 127) / 128);
    tgemm_kernel<<<grid, 256, TG_SMEM_BYTES>>>(Ah, Al, gidx, Bh, Bl, ldb, bias,
                                               C, Ch, Cl, M, Nfull, K, relu, accum);
}

static void launch_wt_conv(const float* W, int K, int N,
                           __nv_bfloat16* Th, __nv_bfloat16* Tl, int ldt)
{
    dim3 grid((N + 31) / 32, (ldt + 31) / 32);
    wt_conv_kernel<<<grid, dim3(32, 8)>>>(W, K, N, Th, Tl, ldt);
}

extern "C" void kernel_launch(void* const* d_in, const int* in_sizes, int n_in,
                              void* d_out, int out_size)
{
    cudaFuncSetAttribute(tgemm_kernel, cudaFuncAttributeMaxDynamicSharedMemorySize,
                         TG_SMEM_BYTES);

    const float* h_node     = (const float*)d_in[0];
    const float* pos        = (const float*)d_in[1];
    const int*   batch_node = (const int*)  d_in[2];
    const int*   ei         = (const int*)  d_in[3];
    const int*   batch_edge = (const int*)  d_in[4];
    const int*   t          = (const int*)  d_in[5];
    const float* Wne = (const float*)d_in[6];
    const float* Wee = (const float*)d_in[7];
    const float* We1 = (const float*)d_in[8];
    const float* be1 = (const float*)d_in[9];
    const float* We2 = (const float*)d_in[10];
    const float* be2 = (const float*)d_in[11];
    const float* Wm  = (const float*)d_in[12];
    const float* bm  = (const float*)d_in[13];
    const float* Wn1 = (const float*)d_in[14];
    const float* bn1 = (const float*)d_in[15];
    const float* Wn2 = (const float*)d_in[16];
    const float* bn2 = (const float*)d_in[17];
    const float* Wd1 = (const float*)d_in[18];
    const float* bd1 = (const float*)d_in[19];
    const float* Wd2 = (const float*)d_in[20];
    const float* bd2 = (const float*)d_in[21];
    const float* Wd3 = (const float*)d_in[22];
    const float* bd3 = (const float*)d_in[23];

    const int N  = in_sizes[0] / 16;   // 20000
    const int E  = in_sizes[4];        // 200000
    const int nh = E / 2;              // 100000
    const int* src = ei;
    const int* dst = ei + E;

    float* hn    = sym_addr(g_hn);
    float* he    = sym_addr(g_he);
    float* hid_e = sym_addr(g_hid_e);
    float* msg   = sym_addr(g_msg);
    float* agg   = sym_addr(g_agg);
    float* hid_n = sym_addr(g_hid_n);
    float* dist  = sym_addr(g_dist);
    float* tn    = sym_addr(g_tn);
    float* te    = sym_addr(g_te);

    __nv_bfloat16 *hn_h = sym_addr(g_hn_h), *hn_l = sym_addr(g_hn_l);
    __nv_bfloat16 *he_h = sym_addr(g_he_h), *he_l = sym_addr(g_he_l);
    __nv_bfloat16 *hide_h = sym_addr(g_hide_h), *hide_l = sym_addr(g_hide_l);
    __nv_bfloat16 *agg_h = sym_addr(g_agg_h), *agg_l = sym_addr(g_agg_l);
    __nv_bfloat16 *hidn_h = sym_addr(g_hidn_h), *hidn_l = sym_addr(g_hidn_l);
    __nv_bfloat16 *symh = sym_addr(g_sym_h), *syml = sym_addr(g_sym_l);
    __nv_bfloat16 *pair_h = sym_addr(g_pair_h), *pair_l = sym_addr(g_pair_l);
    __nv_bfloat16 *dec1_h = sym_addr(g_dec1_h), *dec1_l = sym_addr(g_dec1_l);

    __nv_bfloat16 *We1t_h = sym_addr(g_We1t_h), *We1t_l = sym_addr(g_We1t_l);
    __nv_bfloat16 *We2t_h = sym_addr(g_We2t_h), *We2t_l = sym_addr(g_We2t_l);
    __nv_bfloat16 *Wmt_h  = sym_addr(g_Wmt_h),  *Wmt_l  = sym_addr(g_Wmt_l);
    __nv_bfloat16 *Wn1t_h = sym_addr(g_Wn1t_h), *Wn1t_l = sym_addr(g_Wn1t_l);
    __nv_bfloat16 *Wn2t_h = sym_addr(g_Wn2t_h), *Wn2t_l = sym_addr(g_Wn2t_l);
    __nv_bfloat16 *Wd1t_h = sym_addr(g_Wd1t_h), *Wd1t_l = sym_addr(g_Wd1t_l);
    __nv_bfloat16 *Wd2t_h = sym_addr(g_Wd2t_h), *Wd2t_l = sym_addr(g_Wd2t_l);

    // --- weight transpose + split (tiny) ---
    for (int l = 0; l < 2; l++) {
        launch_wt_conv(We1 + (size_t)l * 657 * 128, 657, 128,
                       We1t_h + (size_t)l * 128 * 664, We1t_l + (size_t)l * 128 * 664, 664);
        launch_wt_conv(We2 + (size_t)l * 128 * 128, 128, 128,
                       We2t_h + (size_t)l * 128 * 128, We2t_l + (size_t)l * 128 * 128, 128);
        launch_wt_conv(Wm + (size_t)l * 384 * 256, 384, 256,
                       Wmt_h + (size_t)l * 256 * 384, Wmt_l + (size_t)l * 256 * 384, 384);
        launch_wt_conv(Wn1 + (size_t)l * 513 * 256, 513, 256,
                       Wn1t_h + (size_t)l * 256 * 520, Wn1t_l + (size_t)l * 256 * 520, 520);
        launch_wt_conv(Wn2 + (size_t)l * 256 * 256, 256, 256,
                       Wn2t_h + (size_t)l * 256 * 256, Wn2t_l + (size_t)l * 256 * 256, 256);
    }
    launch_wt_conv(Wd1, 384, 128, Wd1t_h, Wd1t_l, 384);
    launch_wt_conv(Wd2, 128, 128, Wd2t_h, Wd2t_l, 128);

    // --- embeddings / geometric features ---
    init_node_kernel<<<N, 256>>>(h_node, batch_node, t, Wne, hn, hn_h, hn_l, tn);
    init_edge_kernel<<<E, 128>>>(h_node, pos, ei, batch_edge, t, Wee,
                                 he, he_h, he_l, dist, te, E);

    // --- L = 2 NodeEdgeNet blocks ---
    for (int l = 0; l < 2; l++) {
        const float* be1l = be1 + (size_t)l * 128;
        const float* be2l = be2 + (size_t)l * 128;
        const float* bml  = bm  + (size_t)l * 256;
        const float* bn1l = bn1 + (size_t)l * 256;
        const float* bn2l = bn2 + (size_t)l * 256;
        const float* We1tail = We1 + (size_t)l * 657 * 128 + 640 * 128;
        const float* Wn1tail = Wn1 + (size_t)l * 513 * 256 + 512 * 256;

        const __nv_bfloat16* We1th = We1t_h + (size_t)l * 128 * 664;
        const __nv_bfloat16* We1tl = We1t_l + (size_t)l * 128 * 664;
        const __nv_bfloat16* We2th = We2t_h + (size_t)l * 128 * 128;
        const __nv_bfloat16* We2tl = We2t_l + (size_t)l * 128 * 128;
        const __nv_bfloat16* Wmth  = Wmt_h  + (size_t)l * 256 * 384;
        const __nv_bfloat16* Wmtl  = Wmt_l  + (size_t)l * 256 * 384;
        const __nv_bfloat16* Wn1th = Wn1t_h + (size_t)l * 256 * 520;
        const __nv_bfloat16* Wn1tl = Wn1t_l + (size_t)l * 256 * 520;
        const __nv_bfloat16* Wn2th = Wn2t_h + (size_t)l * 256 * 256;
        const __nv_bfloat16* Wn2tl = Wn2t_l + (size_t)l * 256 * 256;

        // hidden_e = relu([h_e, hn[src], hn[dst], dist, te] @ We1 + be1)
        launch_tgemm(he_h, he_l, nullptr, We1th,       We1tl,       664, be1l,
                     hid_e, nullptr, nullptr, E, 128, 128, 0, 0);
        launch_tgemm(hn_h, hn_l, src,     We1th + 128, We1tl + 128, 664, nullptr,
                     hid_e, nullptr, nullptr, E, 128, 256, 0, 1);
        launch_tgemm(hn_h, hn_l, dst,     We1th + 384, We1tl + 384, 664, nullptr,
                     hid_e, nullptr, nullptr, E, 128, 256, 0, 1);
        edge_finish_kernel<<<E, 128>>>(dist, te, We1tail, hid_e, hide_h, hide_l);

        // h_e += hidden_e @ We2 + be2 (residual) + planes
        launch_tgemm(hide_h, hide_l, nullptr, We2th, We2tl, 128, be2l,
                     he, he_h, he_l, E, 128, 128, 0, 1);

        // msg = relu([hn[src], h_e] @ Wm + bm)
        launch_tgemm(hn_h, hn_l, src,     Wmth,       Wmtl,       384, bml,
                     msg, nullptr, nullptr, E, 256, 256, 0, 0);
        launch_tgemm(he_h, he_l, nullptr, Wmth + 256, Wmtl + 256, 384, nullptr,
                     msg, nullptr, nullptr, E, 256, 128, 1, 1);

        // agg = segment_sum(msg, dst) + planes
        zero_kernel<<<(N * 256 + 255) / 256, 256>>>(agg, N * 256);
        scatter_add_kernel<<<(int)(((size_t)E * 64 + 255) / 256), 256>>>(msg, dst, agg, E);
        act_conv_kernel<<<(N * 64 + 255) / 256, 256>>>(agg, agg_h, agg_l, N * 64);

        // hidden_n = relu([h_n, agg, node_time] @ Wn1 + bn1)
        launch_tgemm(hn_h,  hn_l,  nullptr, Wn1th,       Wn1tl,       520, bn1l,
                     hid_n, nullptr, nullptr, N, 256, 256, 0, 0);
        launch_tgemm(agg_h, agg_l, nullptr, Wn1th + 256, Wn1tl + 256, 520, nullptr,
                     hid_n, nullptr, nullptr, N, 256, 256, 0, 1);
        node_finish_kernel<<<N, 256>>>(tn, Wn1tail, hid_n, hidn_h, hidn_l);

        // h_n += hidden_n @ Wn2 + bn2 + planes
        launch_tgemm(hidn_h, hidn_l, nullptr, Wn2th, Wn2tl, 256, bn2l,
                     hn, hn_h, hn_l, N, 256, 256, 0, 1);
    }

    // --- decode ---
    float* dec1 = hid_e + (size_t)nh * 128;
    float* dec2 = msg + (size_t)nh * 256;

    sym_kernel <<<(int)(((size_t)nh * 128 + 255) / 256), 256>>>(he, symh, syml, nh);
    pair_kernel<<<(int)(((size_t)nh * 256 + 255) / 256), 256>>>(hn, ei, pair_h, pair_l, nh, E);

    launch_tgemm(symh,   syml,   nullptr, Wd1t_h,       Wd1t_l,       384, bd1,
                 dec1, nullptr, nullptr, nh, 128, 128, 0, 0);
    launch_tgemm(pair_h, pair_l, nullptr, Wd1t_h + 128, Wd1t_l + 128, 384, nullptr,
                 dec1, dec1_h, dec1_l, nh, 128, 256, 1, 1);
    launch_tgemm(dec1_h, dec1_l, nullptr, Wd2t_h,       Wd2t_l,       128, bd2,
                 dec2, nullptr, nullptr, nh, 128, 128, 1, 0);

    final_kernel<<<nh, 128>>>(dec2, Wd3, bd3, (float*)d_out);
}

// round 6
// speedup vs baseline: 1.8342x; 1.2248x over previous
#include <cuda_runtime.h>
#include <cuda_bf16.h>
#include <math.h>
#include <stdint.h>

// ===========================================================================
// BondPredictor: all GEMMs on HMMA (mma.sync bf16) via bf16x3 split precision,
// with multi-segment fused concat GEMMs (accumulate across segments in regs).
// N=20000 nodes, E=200000 edges, ND=256, ED=128, L=2, NE=5.
// ===========================================================================

#define N_MAX 20000
#define E_MAX 200000
#define NH_MAX (E_MAX / 2)

// ------------------------- fp32 scratch -----------------------------------
__device__ float g_hn [(size_t)N_MAX * 256];
__device__ float g_he [(size_t)E_MAX * 128];
__device__ float g_msg[(size_t)E_MAX * 256];   // reused as dec2 in decode
__device__ float g_agg[(size_t)N_MAX * 256];
__device__ float g_tn [N_MAX];

// ------------------------- bf16 hi/lo planes (activations) -----------------
__device__ __nv_bfloat16 g_hn_h  [(size_t)N_MAX * 256];
__device__ __nv_bfloat16 g_hn_l  [(size_t)N_MAX * 256];
__device__ __nv_bfloat16 g_he_h  [(size_t)E_MAX * 128];
__device__ __nv_bfloat16 g_he_l  [(size_t)E_MAX * 128];
__device__ __nv_bfloat16 g_hide_h[(size_t)E_MAX * 128];
__device__ __nv_bfloat16 g_hide_l[(size_t)E_MAX * 128];
__device__ __nv_bfloat16 g_agg_h [(size_t)N_MAX * 256];
__device__ __nv_bfloat16 g_agg_l [(size_t)N_MAX * 256];
__device__ __nv_bfloat16 g_hidn_h[(size_t)N_MAX * 256];
__device__ __nv_bfloat16 g_hidn_l[(size_t)N_MAX * 256];
__device__ __nv_bfloat16 g_exte_h[(size_t)E_MAX * 64];
__device__ __nv_bfloat16 g_exte_l[(size_t)E_MAX * 64];
__device__ __nv_bfloat16 g_extn_h[(size_t)N_MAX * 64];
__device__ __nv_bfloat16 g_extn_l[(size_t)N_MAX * 64];
__device__ __nv_bfloat16 g_sym_h [(size_t)NH_MAX * 128];
__device__ __nv_bfloat16 g_sym_l [(size_t)NH_MAX * 128];
__device__ __nv_bfloat16 g_pair_h[(size_t)NH_MAX * 256];
__device__ __nv_bfloat16 g_pair_l[(size_t)NH_MAX * 256];
__device__ __nv_bfloat16 g_dec1_h[(size_t)NH_MAX * 128];
__device__ __nv_bfloat16 g_dec1_l[(size_t)NH_MAX * 128];

// ------------------------- transposed+split weights [N, Ktot] --------------
__device__ __nv_bfloat16 g_We1t_h[2 * 128 * 704];
__device__ __nv_bfloat16 g_We1t_l[2 * 128 * 704];
__device__ __nv_bfloat16 g_We2t_h[2 * 128 * 128];
__device__ __nv_bfloat16 g_We2t_l[2 * 128 * 128];
__device__ __nv_bfloat16 g_Wmt_h [2 * 256 * 384];
__device__ __nv_bfloat16 g_Wmt_l [2 * 256 * 384];
__device__ __nv_bfloat16 g_Wn1t_h[2 * 256 * 576];
__device__ __nv_bfloat16 g_Wn1t_l[2 * 256 * 576];
__device__ __nv_bfloat16 g_Wn2t_h[2 * 256 * 256];
__device__ __nv_bfloat16 g_Wn2t_l[2 * 256 * 256];
__device__ __nv_bfloat16 g_Wd1t_h[128 * 384];
__device__ __nv_bfloat16 g_Wd1t_l[128 * 384];
__device__ __nv_bfloat16 g_Wd2t_h[128 * 128];
__device__ __nv_bfloat16 g_Wd2t_l[128 * 128];

// ===========================================================================
// PTX helpers (sm_80-era: valid on plain sm_103 target)
// ===========================================================================
__device__ __forceinline__ uint32_t smem_u32(const void* p) {
    uint32_t a;
    asm("{ .reg .u64 t; cvta.to.shared.u64 t, %1; cvt.u32.u64 %0, t; }"
        : "=r"(a) : "l"(p));
    return a;
}
__device__ __forceinline__ void cp16(uint32_t dst, const void* src) {
    asm volatile("cp.async.cg.shared.global [%0], [%1], 16;" :: "r"(dst), "l"(src));
}
#define CP_COMMIT()  asm volatile("cp.async.commit_group;" ::: "memory")
#define CP_WAIT(n)   asm volatile("cp.async.wait_group %0;" :: "n"(n) : "memory")

#define LDSM4(r0, r1, r2, r3, addr) \
    asm volatile("ldmatrix.sync.aligned.m8n8.x4.shared.b16 {%0,%1,%2,%3}, [%4];" \
                 : "=r"(r0), "=r"(r1), "=r"(r2), "=r"(r3) : "r"(addr))

#define MMA16816(d, a, b0, b1) \
    asm volatile("mma.sync.aligned.m16n8k16.row.col.f32.bf16.bf16.f32 " \
                 "{%0,%1,%2,%3},{%4,%5,%6,%7},{%8,%9},{%0,%1,%2,%3};" \
                 : "+f"((d)[0]), "+f"((d)[1]), "+f"((d)[2]), "+f"((d)[3]) \
                 : "r"((a)[0]), "r"((a)[1]), "r"((a)[2]), "r"((a)[3]), \
                   "r"(b0), "r"(b1))

__device__ __forceinline__ void bf16_split(float x, __nv_bfloat16& h, __nv_bfloat16& l) {
    h = __float2bfloat16(x);
    l = __float2bfloat16(x - __bfloat162float(h));
}

// ===========================================================================
// Multi-segment HMMA GEMM.
//   C[M, Nfull] = op( concat_s A_s[gidx_s?][K_s] @ Bt^T + bias )
//   Segments' planes are bf16 hi/lo; Bt transposed planes [Nfull, Ktot].
//   bf16x3: 3 passes over Ktot in 64-k chunks; pass p selects planes
//   (A: hi,hi,lo ; B: hi,lo,hi). All K_s multiples of 64.
//   Block 128x128, 8 warps (4m x 2n -> 32x64 warp tiles), BK=64 SW128,
//   cp.async double buffering. Epilogue: bias/accum/relu; optional fp32 C
//   (null = skip) and optional bf16 plane outputs.
// ===========================================================================
#define TG_SMEM_BYTES 65536

struct Seg { const __nv_bfloat16* h; const __nv_bfloat16* l; const int* g; int K; int off; };
struct SegList { Seg s[4]; int n; int Ktot; };

__global__ __launch_bounds__(256)
void tgemm_kernel(SegList segs,
                  const __nv_bfloat16* __restrict__ Bhi,   // [Nfull, Ktot]
                  const __nv_bfloat16* __restrict__ Blo,
                  const float* __restrict__ bias,
                  float* __restrict__ C,
                  __nv_bfloat16* __restrict__ Chi,
                  __nv_bfloat16* __restrict__ Clo,
                  int M, int Nfull, int relu, int accum)
{
    extern __shared__ char smem[];
    const uint32_t sbase = smem_u32(smem);
    const int tid = threadIdx.x;
    const int L   = tid & 31;
    const int wid = tid >> 5;
    const int wm  = wid >> 1;      // 0..3
    const int wn  = wid & 1;       // 0..1
    const int bn0 = blockIdx.x * 128;
    const int bm0 = blockIdx.y * 128;
    const int Ktot = segs.Ktot;

    // ---- staging setup: thread -> (row srow 0..127, half sh 0..1) ----
    const int srow = tid >> 1;
    const int sh   = tid & 1;
    uint32_t soff[4];
#pragma unroll
    for (int i = 0; i < 4; i++) {
        int ch = sh * 4 + i;
        soff[i] = (uint32_t)(srow * 128 + ((ch ^ (srow & 7)) * 16));
    }
    const int arow_g = bm0 + srow;
    const __nv_bfloat16* ah[4];
    const __nv_bfloat16* al[4];
#pragma unroll
    for (int s = 0; s < 4; s++) {
        if (s < segs.n) {
            int gr = 0;
            if (arow_g < M) gr = segs.s[s].g ? segs.s[s].g[arow_g] : arow_g;
            ah[s] = segs.s[s].h + (size_t)gr * segs.s[s].K + sh * 32;
            al[s] = segs.s[s].l + (size_t)gr * segs.s[s].K + sh * 32;
        } else {
            ah[s] = segs.s[0].h;
            al[s] = segs.s[0].l;
        }
    }
    const __nv_bfloat16* bph = Bhi + (size_t)(bn0 + srow) * Ktot + sh * 32;
    const __nv_bfloat16* bpl = Blo + (size_t)(bn0 + srow) * Ktot + sh * 32;

    const int per = Ktot / 64;     // chunks per pass
    const int nch = 3 * per;

    // ---- ldmatrix per-lane address precompute ----
    uint32_t a_rbase[2], b_rbase[4];
    int a_rsw[2], b_rsw[4];
    const int a_csel = L >> 4;
    const int b_csel = (L >> 3) & 1;
#pragma unroll
    for (int mf = 0; mf < 2; mf++) {
        int r = wm * 32 + mf * 16 + ((L >> 3) & 1) * 8 + (L & 7);
        a_rbase[mf] = (uint32_t)(r * 128);
        a_rsw[mf] = r & 7;
    }
#pragma unroll
    for (int nf2 = 0; nf2 < 4; nf2++) {
        int r = wn * 64 + nf2 * 16 + (L >> 4) * 8 + (L & 7);
        b_rbase[nf2] = (uint32_t)(r * 128);
        b_rsw[nf2] = r & 7;
    }

    float acc[2][8][4];
#pragma unroll
    for (int mf = 0; mf < 2; mf++)
#pragma unroll
        for (int nf = 0; nf < 8; nf++)
#pragma unroll
            for (int q = 0; q < 4; q++) acc[mf][nf][q] = 0.0f;

    // ---- stage one chunk into buffer `bufsel` ----
    auto stage = [&](int c) {
        const int bufsel = c & 1;
        const int p  = c / per;
        const int k0 = (c - p * per) * 64;
        int s = 0;
#pragma unroll
        for (int q = 1; q < 4; q++)
            if (k0 >= segs.s[q].off) s = q;   // unused segs: off = Ktot sentinel
        const int lk = k0 - segs.s[s].off;
        const __nv_bfloat16* as = ((p == 2) ? al[s] : ah[s]) + lk;
        const __nv_bfloat16* bs = ((p == 1) ? bpl : bph) + k0;
        const uint32_t ab = sbase + bufsel * 16384;
        const uint32_t bb = sbase + 32768 + bufsel * 16384;
#pragma unroll
        for (int i = 0; i < 4; i++) {
            cp16(ab + soff[i], as + i * 8);
            cp16(bb + soff[i], bs + i * 8);
        }
        CP_COMMIT();
    };

    stage(0);

    for (int c = 0; c < nch; c++) {
        const int buf = c & 1;
        if (c + 1 < nch) { stage(c + 1); CP_WAIT(1); }
        else             { CP_WAIT(0); }
        __syncthreads();

        const uint32_t Ab = sbase + buf * 16384;
        const uint32_t Bb = sbase + 32768 + buf * 16384;
#pragma unroll
        for (int j = 0; j < 4; j++) {
            uint32_t a0[4], a1[4];
            {
                uint32_t ca = (uint32_t)(((2 * j + a_csel) ^ a_rsw[0]) * 16);
                LDSM4(a0[0], a0[1], a0[2], a0[3], Ab + a_rbase[0] + ca);
                uint32_t cb = (uint32_t)(((2 * j + a_csel) ^ a_rsw[1]) * 16);
                LDSM4(a1[0], a1[1], a1[2], a1[3], Ab + a_rbase[1] + cb);
            }
            uint32_t bv[4][4];
#pragma unroll
            for (int nf2 = 0; nf2 < 4; nf2++) {
                uint32_t cb = (uint32_t)(((2 * j + b_csel) ^ b_rsw[nf2]) * 16);
                LDSM4(bv[nf2][0], bv[nf2][1], bv[nf2][2], bv[nf2][3],
                      Bb + b_rbase[nf2] + cb);
            }
#pragma unroll
            for (int nf2 = 0; nf2 < 4; nf2++) {
                MMA16816(acc[0][2 * nf2],     a0, bv[nf2][0], bv[nf2][1]);
                MMA16816(acc[0][2 * nf2 + 1], a0, bv[nf2][2], bv[nf2][3]);
                MMA16816(acc[1][2 * nf2],     a1, bv[nf2][0], bv[nf2][1]);
                MMA16816(acc[1][2 * nf2 + 1], a1, bv[nf2][2], bv[nf2][3]);
            }
        }
        __syncthreads();
    }

    // ---- epilogue ----
#pragma unroll
    for (int mf = 0; mf < 2; mf++) {
#pragma unroll
        for (int nf = 0; nf < 8; nf++) {
            const int col = bn0 + wn * 64 + nf * 8 + (L & 3) * 2;
#pragma unroll
            for (int half = 0; half < 2; half++) {
                const int m = bm0 + wm * 32 + mf * 16 + (L >> 2) + half * 8;
                if (m >= M) continue;
                float v0 = acc[mf][nf][half * 2 + 0];
                float v1 = acc[mf][nf][half * 2 + 1];
                if (bias) { v0 += bias[col]; v1 += bias[col + 1]; }
                const size_t o = (size_t)m * Nfull + col;
                if (C && accum) { v0 += C[o]; v1 += C[o + 1]; }
                if (relu) { v0 = fmaxf(v0, 0.f); v1 = fmaxf(v1, 0.f); }
                if (C) { C[o] = v0; C[o + 1] = v1; }
                if (Chi) {
                    __nv_bfloat16 h0, l0, h1, l1;
                    bf16_split(v0, h0, l0);
                    bf16_split(v1, h1, l1);
                    Chi[o] = h0; Chi[o + 1] = h1;
                    Clo[o] = l0; Clo[o + 1] = l1;
                }
            }
        }
    }
}

// ===========================================================================
// Weight transpose + split: W[K,N] fp32 -> Th/Tl [N, ldt] bf16 (zero-padded)
// ===========================================================================
__global__ void wt_conv_kernel(const float* __restrict__ W, int K, int N,
                               __nv_bfloat16* __restrict__ Th,
                               __nv_bfloat16* __restrict__ Tl, int ldt)
{
    __shared__ float tile[32][33];
    const int k0 = blockIdx.y * 32, n0 = blockIdx.x * 32;
    const int tx = threadIdx.x, ty = threadIdx.y;  // 32x8
    for (int i = ty; i < 32; i += 8) {
        int k = k0 + i, n = n0 + tx;
        tile[i][tx] = (k < K && n < N) ? W[(size_t)k * N + n] : 0.0f;
    }
    __syncthreads();
    for (int i = ty; i < 32; i += 8) {
        int n = n0 + i, k = k0 + tx;
        if (n < N && k < ldt) {
            float x = tile[tx][i];
            __nv_bfloat16 hb, lb;
            bf16_split(x, hb, lb);
            Th[(size_t)n * ldt + k] = hb;
            Tl[(size_t)n * ldt + k] = lb;
        }
    }
}

__global__ void act_conv_kernel(const float* __restrict__ X,
                                __nv_bfloat16* __restrict__ Xh,
                                __nv_bfloat16* __restrict__ Xl, int n4)
{
    int i = blockIdx.x * 256 + threadIdx.x;
    if (i >= n4) return;
    float4 x = ((const float4*)X)[i];
    __nv_bfloat16 hh[4], ll[4];
    bf16_split(x.x, hh[0], ll[0]);
    bf16_split(x.y, hh[1], ll[1]);
    bf16_split(x.z, hh[2], ll[2]);
    bf16_split(x.w, hh[3], ll[3]);
    *(uint2*)(Xh + (size_t)i * 4) = *(uint2*)hh;
    *(uint2*)(Xl + (size_t)i * 4) = *(uint2*)ll;
}

// ===========================================================================
// Elementwise / small kernels
// ===========================================================================
__global__ void init_node_kernel(const float* __restrict__ h_node,
                                 const int* __restrict__ batch_node,
                                 const int* __restrict__ t,
                                 const float* __restrict__ Wne,
                                 float* __restrict__ hn,
                                 __nv_bfloat16* __restrict__ hn_h,
                                 __nv_bfloat16* __restrict__ hn_l,
                                 __nv_bfloat16* __restrict__ extn_h,
                                 __nv_bfloat16* __restrict__ extn_l,
                                 float* __restrict__ tn_out)
{
    int row = blockIdx.x;
    int c = threadIdx.x;  // 256
    __shared__ float hsh[16];
    __shared__ float tn_s;
    if (c < 16) hsh[c] = h_node[row * 16 + c];
    if (c == 0) tn_s = (float)t[batch_node[row]];
    __syncthreads();
    float tn = tn_s;
    float v;
    if (c < 240) {
        v = 0.f;
#pragma unroll
        for (int k = 0; k < 16; k++) v = fmaf(hsh[k], Wne[k * 240 + c], v);
    } else {
        const float step = 1000.0f / 15.0f;
        float dx = tn - (float)(c - 240) * step;
        v = expf((-0.5f / (step * step)) * dx * dx);
    }
    size_t idx = (size_t)row * 256 + c;
    hn[idx] = v;
    __nv_bfloat16 hb, lb; bf16_split(v, hb, lb);
    hn_h[idx] = hb; hn_l[idx] = lb;
    if (c < 64) {
        float ev = (c == 0) ? tn * (1.0f / 1000.0f) : 0.0f;
        __nv_bfloat16 eh, el; bf16_split(ev, eh, el);
        extn_h[(size_t)row * 64 + c] = eh;
        extn_l[(size_t)row * 64 + c] = el;
    }
    if (c == 0) tn_out[row] = tn;
}

__global__ void init_edge_kernel(const float* __restrict__ h_node,
                                 const float* __restrict__ pos,
                                 const int* __restrict__ ei,
                                 const int* __restrict__ batch_edge,
                                 const int* __restrict__ t,
                                 const float* __restrict__ Wee,
                                 float* __restrict__ he,
                                 __nv_bfloat16* __restrict__ he_h,
                                 __nv_bfloat16* __restrict__ he_l,
                                 __nv_bfloat16* __restrict__ exte_h,
                                 __nv_bfloat16* __restrict__ exte_l,
                                 int E)
{
    int e = blockIdx.x;
    int c = threadIdx.x;  // 128
    __shared__ float hsh[32];
    __shared__ float sh[2];
    int s = ei[e], d = ei[E + e];
    if (c < 16)      hsh[c] = h_node[s * 16 + c];
    else if (c < 32) hsh[c] = h_node[d * 16 + (c - 16)];
    if (c == 0) {
        sh[0] = (float)t[batch_edge[e]];
        float dx = pos[d * 3 + 0] - pos[s * 3 + 0];
        float dy = pos[d * 3 + 1] - pos[s * 3 + 1];
        float dz = pos[d * 3 + 2] - pos[s * 3 + 2];
        sh[1] = sqrtf(dx * dx + dy * dy + dz * dz);
    }
    __syncthreads();
    float te = sh[0], dd = sh[1];
    float v;
    if (c < 112) {
        v = 0.f;
#pragma unroll
        for (int k = 0; k < 32; k++) v = fmaf(hsh[k], Wee[k * 112 + c], v);
    } else {
        const float step = 1000.0f / 15.0f;
        float dx = te - (float)(c - 112) * step;
        v = expf((-0.5f / (step * step)) * dx * dx);
    }
    size_t idx = (size_t)e * 128 + c;
    he[idx] = v;
    __nv_bfloat16 hb, lb; bf16_split(v, hb, lb);
    he_h[idx] = hb; he_l[idx] = lb;
    if (c < 64) {
        float ev = 0.0f;
        if (c < 16) {
            const float step = 10.0f / 15.0f;
            float dx = dd - (float)c * step;
            ev = expf((-0.5f / (step * step)) * dx * dx);
        } else if (c == 16) {
            ev = te * (1.0f / 1000.0f);
        }
        __nv_bfloat16 eh, el; bf16_split(ev, eh, el);
        exte_h[(size_t)e * 64 + c] = eh;
        exte_l[(size_t)e * 64 + c] = el;
    }
}

__global__ void zero_kernel(float* __restrict__ p, int n)
{
    int i = blockIdx.x * 256 + threadIdx.x;
    if (i < n) p[i] = 0.0f;
}

// agg[dst[e]] += msg[e]; skip exact zeros (~half post-relu)
__global__ void scatter_add_kernel(const float* __restrict__ msg,
                                   const int* __restrict__ dst,
                                   float* __restrict__ agg, int E)
{
    size_t i = (size_t)blockIdx.x * 256 + threadIdx.x;  // over E*64
    if (i >= (size_t)E * 64) return;
    int e = (int)(i >> 6);
    int c = (int)((i & 63) * 4);
    float4 mv = *(const float4*)&msg[(size_t)e * 256 + c];
    float* ap = &agg[(size_t)dst[e] * 256 + c];
    if (mv.x != 0.0f) atomicAdd(ap + 0, mv.x);
    if (mv.y != 0.0f) atomicAdd(ap + 1, mv.y);
    if (mv.z != 0.0f) atomicAdd(ap + 2, mv.z);
    if (mv.w != 0.0f) atomicAdd(ap + 3, mv.w);
}

__global__ void sym_kernel(const float* __restrict__ he,
                           __nv_bfloat16* __restrict__ oh,
                           __nv_bfloat16* __restrict__ ol, int nh)
{
    size_t i = (size_t)blockIdx.x * 256 + threadIdx.x;
    if (i >= (size_t)nh * 128) return;
    float v = he[i] + he[i + (size_t)nh * 128];
    __nv_bfloat16 hb, lb; bf16_split(v, hb, lb);
    oh[i] = hb; ol[i] = lb;
}

__global__ void pair_kernel(const float* __restrict__ hn, const int* __restrict__ ei,
                            __nv_bfloat16* __restrict__ oh,
                            __nv_bfloat16* __restrict__ ol, int nh, int E)
{
    size_t i = (size_t)blockIdx.x * 256 + threadIdx.x;
    if (i >= (size_t)nh * 256) return;
    int e = (int)(i >> 8);
    int c = (int)(i & 255);
    int s = ei[e], d = ei[E + e];
    float v = hn[(size_t)s * 256 + c] + hn[(size_t)d * 256 + c];
    __nv_bfloat16 hb, lb; bf16_split(v, hb, lb);
    oh[i] = hb; ol[i] = lb;
}

__global__ void final_kernel(const float* __restrict__ h,
                             const float* __restrict__ Wd3,
                             const float* __restrict__ bd3,
                             float* __restrict__ out)
{
    int i = blockIdx.x;
    int c = threadIdx.x;  // 128
    __shared__ float sh[128];
    __shared__ float w[128 * 5];
    sh[c] = h[(size_t)i * 128 + c];
    for (int j = c; j < 640; j += 128) w[j] = Wd3[j];
    __syncthreads();
    if (c < 5) {
        float v = bd3[c];
#pragma unroll 8
        for (int k = 0; k < 128; k++) v = fmaf(sh[k], w[k * 5 + c], v);
        out[i * 5 + c] = v;
    }
}

// ===========================================================================
// Host side
// ===========================================================================
template <typename T>
static T* sym_addr(T* symbol)
{
    void* p = nullptr;
    cudaGetSymbolAddress(&p, (const void*)symbol);
    return (T*)p;
}

static SegList make_segs(int n,
                         const __nv_bfloat16* h0, const __nv_bfloat16* l0, const int* g0, int K0,
                         const __nv_bfloat16* h1 = nullptr, const __nv_bfloat16* l1 = nullptr,
                         const int* g1 = nullptr, int K1 = 0,
                         const __nv_bfloat16* h2 = nullptr, const __nv_bfloat16* l2 = nullptr,
                         const int* g2 = nullptr, int K2 = 0,
                         const __nv_bfloat16* h3 = nullptr, const __nv_bfloat16* l3 = nullptr,
                         const int* g3 = nullptr, int K3 = 0)
{
    SegList sl;
    sl.s[0] = {h0, l0, g0, K0, 0};
    sl.s[1] = {h1, l1, g1, K1, 0};
    sl.s[2] = {h2, l2, g2, K2, 0};
    sl.s[3] = {h3, l3, g3, K3, 0};
    sl.n = n;
    int off = 0;
    for (int i = 0; i < 4; i++) {
        if (i < n) { sl.s[i].off = off; off += sl.s[i].K; }
    }
    sl.Ktot = off;
    for (int i = n; i < 4; i++) sl.s[i].off = off;   // sentinel: never selected
    return sl;
}

static void launch_tgemm(const SegList& segs,
                         const __nv_bfloat16* Bh, const __nv_bfloat16* Bl,
                         const float* bias, float* C,
                         __nv_bfloat16* Ch, __nv_bfloat16* Cl,
                         int M, int Nfull, int relu, int accum)
{
    dim3 grid(Nfull / 128, (M + 127) / 128);
    tgemm_kernel<<<grid, 256, TG_SMEM_BYTES>>>(segs, Bh, Bl, bias, C, Ch, Cl,
                                               M, Nfull, relu, accum);
}

static void launch_wt_conv(const float* W, int K, int N,
                           __nv_bfloat16* Th, __nv_bfloat16* Tl, int ldt)
{
    dim3 grid((N + 31) / 32, (ldt + 31) / 32);
    wt_conv_kernel<<<grid, dim3(32, 8)>>>(W, K, N, Th, Tl, ldt);
}

extern "C" void kernel_launch(void* const* d_in, const int* in_sizes, int n_in,
                              void* d_out, int out_size)
{
    cudaFuncSetAttribute(tgemm_kernel, cudaFuncAttributeMaxDynamicSharedMemorySize,
                         TG_SMEM_BYTES);

    const float* h_node     = (const float*)d_in[0];
    const float* pos        = (const float*)d_in[1];
    const int*   batch_node = (const int*)  d_in[2];
    const int*   ei         = (const int*)  d_in[3];
    const int*   batch_edge = (const int*)  d_in[4];
    const int*   t          = (const int*)  d_in[5];
    const float* Wne = (const float*)d_in[6];
    const float* Wee = (const float*)d_in[7];
    const float* We1 = (const float*)d_in[8];
    const float* be1 = (const float*)d_in[9];
    const float* We2 = (const float*)d_in[10];
    const float* be2 = (const float*)d_in[11];
    const float* Wm  = (const float*)d_in[12];
    const float* bm  = (const float*)d_in[13];
    const float* Wn1 = (const float*)d_in[14];
    const float* bn1 = (const float*)d_in[15];
    const float* Wn2 = (const float*)d_in[16];
    const float* bn2 = (const float*)d_in[17];
    const float* Wd1 = (const float*)d_in[18];
    const float* bd1 = (const float*)d_in[19];
    const float* Wd2 = (const float*)d_in[20];
    const float* bd2 = (const float*)d_in[21];
    const float* Wd3 = (const float*)d_in[22];
    const float* bd3 = (const float*)d_in[23];

    const int N  = in_sizes[0] / 16;   // 20000
    const int E  = in_sizes[4];        // 200000
    const int nh = E / 2;              // 100000
    const int* src = ei;
    const int* dst = ei + E;

    float* hn  = sym_addr(g_hn);
    float* he  = sym_addr(g_he);
    float* msg = sym_addr(g_msg);
    float* agg = sym_addr(g_agg);
    float* tn  = sym_addr(g_tn);

    __nv_bfloat16 *hn_h = sym_addr(g_hn_h), *hn_l = sym_addr(g_hn_l);
    __nv_bfloat16 *he_h = sym_addr(g_he_h), *he_l = sym_addr(g_he_l);
    __nv_bfloat16 *hide_h = sym_addr(g_hide_h), *hide_l = sym_addr(g_hide_l);
    __nv_bfloat16 *agg_h = sym_addr(g_agg_h), *agg_l = sym_addr(g_agg_l);
    __nv_bfloat16 *hidn_h = sym_addr(g_hidn_h), *hidn_l = sym_addr(g_hidn_l);
    __nv_bfloat16 *exte_h = sym_addr(g_exte_h), *exte_l = sym_addr(g_exte_l);
    __nv_bfloat16 *extn_h = sym_addr(g_extn_h), *extn_l = sym_addr(g_extn_l);
    __nv_bfloat16 *symh = sym_addr(g_sym_h), *syml = sym_addr(g_sym_l);
    __nv_bfloat16 *pair_h = sym_addr(g_pair_h), *pair_l = sym_addr(g_pair_l);
    __nv_bfloat16 *dec1_h = sym_addr(g_dec1_h), *dec1_l = sym_addr(g_dec1_l);

    __nv_bfloat16 *We1t_h = sym_addr(g_We1t_h), *We1t_l = sym_addr(g_We1t_l);
    __nv_bfloat16 *We2t_h = sym_addr(g_We2t_h), *We2t_l = sym_addr(g_We2t_l);
    __nv_bfloat16 *Wmt_h  = sym_addr(g_Wmt_h),  *Wmt_l  = sym_addr(g_Wmt_l);
    __nv_bfloat16 *Wn1t_h = sym_addr(g_Wn1t_h), *Wn1t_l = sym_addr(g_Wn1t_l);
    __nv_bfloat16 *Wn2t_h = sym_addr(g_Wn2t_h), *Wn2t_l = sym_addr(g_Wn2t_l);
    __nv_bfloat16 *Wd1t_h = sym_addr(g_Wd1t_h), *Wd1t_l = sym_addr(g_Wd1t_l);
    __nv_bfloat16 *Wd2t_h = sym_addr(g_Wd2t_h), *Wd2t_l = sym_addr(g_Wd2t_l);

    // --- weight transpose + split (tiny; zero-pads K -> ldt) ---
    for (int l = 0; l < 2; l++) {
        launch_wt_conv(We1 + (size_t)l * 657 * 128, 657, 128,
                       We1t_h + (size_t)l * 128 * 704, We1t_l + (size_t)l * 128 * 704, 704);
        launch_wt_conv(We2 + (size_t)l * 128 * 128, 128, 128,
                       We2t_h + (size_t)l * 128 * 128, We2t_l + (size_t)l * 128 * 128, 128);
        launch_wt_conv(Wm + (size_t)l * 384 * 256, 384, 256,
                       Wmt_h + (size_t)l * 256 * 384, Wmt_l + (size_t)l * 256 * 384, 384);
        launch_wt_conv(Wn1 + (size_t)l * 513 * 256, 513, 256,
                       Wn1t_h + (size_t)l * 256 * 576, Wn1t_l + (size_t)l * 256 * 576, 576);
        launch_wt_conv(Wn2 + (size_t)l * 256 * 256, 256, 256,
                       Wn2t_h + (size_t)l * 256 * 256, Wn2t_l + (size_t)l * 256 * 256, 256);
    }
    launch_wt_conv(Wd1, 384, 128, Wd1t_h, Wd1t_l, 384);
    launch_wt_conv(Wd2, 128, 128, Wd2t_h, Wd2t_l, 128);

    // --- embeddings / geometric features (+ ext segments) ---
    init_node_kernel<<<N, 256>>>(h_node, batch_node, t, Wne, hn, hn_h, hn_l,
                                 extn_h, extn_l, tn);
    init_edge_kernel<<<E, 128>>>(h_node, pos, ei, batch_edge, t, Wee,
                                 he, he_h, he_l, exte_h, exte_l, E);

    // --- L = 2 NodeEdgeNet blocks ---
    for (int l = 0; l < 2; l++) {
        const float* be1l = be1 + (size_t)l * 128;
        const float* be2l = be2 + (size_t)l * 128;
        const float* bml  = bm  + (size_t)l * 256;
        const float* bn1l = bn1 + (size_t)l * 256;
        const float* bn2l = bn2 + (size_t)l * 256;

        const __nv_bfloat16* We1th = We1t_h + (size_t)l * 128 * 704;
        const __nv_bfloat16* We1tl = We1t_l + (size_t)l * 128 * 704;
        const __nv_bfloat16* We2th = We2t_h + (size_t)l * 128 * 128;
        const __nv_bfloat16* We2tl = We2t_l + (size_t)l * 128 * 128;
        const __nv_bfloat16* Wmth  = Wmt_h  + (size_t)l * 256 * 384;
        const __nv_bfloat16* Wmtl  = Wmt_l  + (size_t)l * 256 * 384;
        const __nv_bfloat16* Wn1th = Wn1t_h + (size_t)l * 256 * 576;
        const __nv_bfloat16* Wn1tl = Wn1t_l + (size_t)l * 256 * 576;
        const __nv_bfloat16* Wn2th = Wn2t_h + (size_t)l * 256 * 256;
        const __nv_bfloat16* Wn2tl = Wn2t_l + (size_t)l * 256 * 256;

        // hidden_e = relu([h_e | hn[src] | hn[dst] | ext_e] @ We1t^T + be1)
        // -> planes only
        launch_tgemm(make_segs(4,
                         he_h, he_l, nullptr, 128,
                         hn_h, hn_l, src,     256,
                         hn_h, hn_l, dst,     256,
                         exte_h, exte_l, nullptr, 64),
                     We1th, We1tl, be1l, nullptr, hide_h, hide_l, E, 128, 1, 0);

        // h_e += hidden_e @ We2 + be2 (residual, fp32) + planes
        launch_tgemm(make_segs(1, hide_h, hide_l, nullptr, 128),
                     We2th, We2tl, be2l, he, he_h, he_l, E, 128, 0, 1);

        // msg = relu([hn[src] | h_e] @ Wm + bm) -> fp32 only (for scatter)
        launch_tgemm(make_segs(2,
                         hn_h, hn_l, src, 256,
                         he_h, he_l, nullptr, 128),
                     Wmth, Wmtl, bml, msg, nullptr, nullptr, E, 256, 1, 0);

        // agg = segment_sum(msg, dst) + planes
        zero_kernel<<<(N * 256 + 255) / 256, 256>>>(agg, N * 256);
        scatter_add_kernel<<<(int)(((size_t)E * 64 + 255) / 256), 256>>>(msg, dst, agg, E);
        act_conv_kernel<<<(N * 64 + 255) / 256, 256>>>(agg, agg_h, agg_l, N * 64);

        // hidden_n = relu([h_n | agg | ext_n] @ Wn1 + bn1) -> planes only
        launch_tgemm(make_segs(3,
                         hn_h, hn_l, nullptr, 256,
                         agg_h, agg_l, nullptr, 256,
                         extn_h, extn_l, nullptr, 64),
                     Wn1th, Wn1tl, bn1l, nullptr, hidn_h, hidn_l, N, 256, 1, 0);

        // h_n += hidden_n @ Wn2 + bn2 (residual, fp32) + planes
        launch_tgemm(make_segs(1, hidn_h, hidn_l, nullptr, 256),
                     Wn2th, Wn2tl, bn2l, hn, hn_h, hn_l, N, 256, 0, 1);
    }

    // --- decode ---
    float* dec2 = msg;   // msg free after last layer

    sym_kernel <<<(int)(((size_t)nh * 128 + 255) / 256), 256>>>(he, symh, syml, nh);
    pair_kernel<<<(int)(((size_t)nh * 256 + 255) / 256), 256>>>(hn, ei, pair_h, pair_l, nh, E);

    // dec1 = relu([sym | pair] @ Wd1 + bd1) -> planes only
    launch_tgemm(make_segs(2,
                     symh, syml, nullptr, 128,
                     pair_h, pair_l, nullptr, 256),
                 Wd1t_h, Wd1t_l, bd1, nullptr, dec1_h, dec1_l, nh, 128, 1, 0);

    // dec2 = relu(dec1 @ Wd2 + bd2) -> fp32 (for final)
    launch_tgemm(make_segs(1, dec1_h, dec1_l, nullptr, 128),
                 Wd2t_h, Wd2t_l, bd2, dec2, nullptr, nullptr, nh, 128, 1, 0);

    final_kernel<<<nh, 128>>>(dec2, Wd3, bd3, (float*)d_out);
}

// round 9
// speedup vs baseline: 1.9914x; 1.0857x over previous
#include <cuda_runtime.h>
#include <cuda_bf16.h>
#include <math.h>
#include <stdint.h>

// ===========================================================================
// BondPredictor: all GEMMs on HMMA (mma.sync bf16) via bf16x3 split precision,
// multi-segment fused concat GEMMs, fused scatter epilogue, fused final proj.
// N=20000 nodes, E=200000 edges, ND=256, ED=128, L=2, NE=5.
// ===========================================================================

#define N_MAX 20000
#define E_MAX 200000
#define NH_MAX (E_MAX / 2)

// ------------------------- fp32 scratch -----------------------------------
__device__ float g_hn [(size_t)N_MAX * 256];
__device__ float g_he [(size_t)E_MAX * 128];
__device__ float g_agg[(size_t)N_MAX * 256];
__device__ float g_tn [N_MAX];

// ------------------------- bf16 hi/lo planes (activations) -----------------
__device__ __nv_bfloat16 g_hn_h  [(size_t)N_MAX * 256];
__device__ __nv_bfloat16 g_hn_l  [(size_t)N_MAX * 256];
__device__ __nv_bfloat16 g_he_h  [(size_t)E_MAX * 128];
__device__ __nv_bfloat16 g_he_l  [(size_t)E_MAX * 128];
__device__ __nv_bfloat16 g_hide_h[(size_t)E_MAX * 128];
__device__ __nv_bfloat16 g_hide_l[(size_t)E_MAX * 128];
__device__ __nv_bfloat16 g_agg_h [(size_t)N_MAX * 256];
__device__ __nv_bfloat16 g_agg_l [(size_t)N_MAX * 256];
__device__ __nv_bfloat16 g_hidn_h[(size_t)N_MAX * 256];
__device__ __nv_bfloat16 g_hidn_l[(size_t)N_MAX * 256];
__device__ __nv_bfloat16 g_exte_h[(size_t)E_MAX * 64];
__device__ __nv_bfloat16 g_exte_l[(size_t)E_MAX * 64];
__device__ __nv_bfloat16 g_extn_h[(size_t)N_MAX * 64];
__device__ __nv_bfloat16 g_extn_l[(size_t)N_MAX * 64];
__device__ __nv_bfloat16 g_sym_h [(size_t)NH_MAX * 128];
__device__ __nv_bfloat16 g_sym_l [(size_t)NH_MAX * 128];
__device__ __nv_bfloat16 g_pair_h[(size_t)NH_MAX * 256];
__device__ __nv_bfloat16 g_pair_l[(size_t)NH_MAX * 256];
__device__ __nv_bfloat16 g_dec1_h[(size_t)NH_MAX * 128];
__device__ __nv_bfloat16 g_dec1_l[(size_t)NH_MAX * 128];

// ------------------------- transposed+split weights [N, Ktot] --------------
__device__ __nv_bfloat16 g_We1t_h[2 * 128 * 704];
__device__ __nv_bfloat16 g_We1t_l[2 * 128 * 704];
__device__ __nv_bfloat16 g_We2t_h[2 * 128 * 128];
__device__ __nv_bfloat16 g_We2t_l[2 * 128 * 128];
__device__ __nv_bfloat16 g_Wmt_h [2 * 256 * 384];
__device__ __nv_bfloat16 g_Wmt_l [2 * 256 * 384];
__device__ __nv_bfloat16 g_Wn1t_h[2 * 256 * 576];
__device__ __nv_bfloat16 g_Wn1t_l[2 * 256 * 576];
__device__ __nv_bfloat16 g_Wn2t_h[2 * 256 * 256];
__device__ __nv_bfloat16 g_Wn2t_l[2 * 256 * 256];
__device__ __nv_bfloat16 g_Wd1t_h[128 * 384];
__device__ __nv_bfloat16 g_Wd1t_l[128 * 384];
__device__ __nv_bfloat16 g_Wd2t_h[128 * 128];
__device__ __nv_bfloat16 g_Wd2t_l[128 * 128];

// ===========================================================================
// PTX helpers (sm_80-era: valid on plain sm_103 target)
// ===========================================================================
__device__ __forceinline__ uint32_t smem_u32(const void* p) {
    uint32_t a;
    asm("{ .reg .u64 t; cvta.to.shared.u64 t, %1; cvt.u32.u64 %0, t; }"
        : "=r"(a) : "l"(p));
    return a;
}
__device__ __forceinline__ void cp16(uint32_t dst, const void* src) {
    asm volatile("cp.async.cg.shared.global [%0], [%1], 16;" :: "r"(dst), "l"(src));
}
#define CP_COMMIT()  asm volatile("cp.async.commit_group;" ::: "memory")
#define CP_WAIT(n)   asm volatile("cp.async.wait_group %0;" :: "n"(n) : "memory")

#define LDSM4(r0, r1, r2, r3, addr) \
    asm volatile("ldmatrix.sync.aligned.m8n8.x4.shared.b16 {%0,%1,%2,%3}, [%4];" \
                 : "=r"(r0), "=r"(r1), "=r"(r2), "=r"(r3) : "r"(addr))

#define MMA16816(d, a, b0, b1) \
    asm volatile("mma.sync.aligned.m16n8k16.row.col.f32.bf16.bf16.f32 " \
                 "{%0,%1,%2,%3},{%4,%5,%6,%7},{%8,%9},{%0,%1,%2,%3};" \
                 : "+f"((d)[0]), "+f"((d)[1]), "+f"((d)[2]), "+f"((d)[3]) \
                 : "r"((a)[0]), "r"((a)[1]), "r"((a)[2]), "r"((a)[3]), \
                   "r"(b0), "r"(b1))

__device__ __forceinline__ void bf16_split(float x, __nv_bfloat16& h, __nv_bfloat16& l) {
    h = __float2bfloat16(x);
    l = __float2bfloat16(x - __bfloat162float(h));
}

// ===========================================================================
// Multi-segment HMMA GEMM (bf16x3).
//   Epilogue modes:
//     - scat != null : atomicAdd rows into C at row scat[m] (skip zeros)
//     - out5 != null : project 128-wide rows through Wd3 (128x5) -> out5
//     - else         : optional fp32 C (bias/accum/relu) + optional planes
// ===========================================================================
#define TG_SMEM_BYTES 65536

struct Seg { const __nv_bfloat16* h; const __nv_bfloat16* l; const int* g; int K; int off; };
struct SegList { Seg s[4]; int n; int Ktot; };

__global__ __launch_bounds__(256)
void tgemm_kernel(SegList segs,
                  const __nv_bfloat16* __restrict__ Bhi,   // [Nfull, Ktot]
                  const __nv_bfloat16* __restrict__ Blo,
                  const float* __restrict__ bias,
                  float* __restrict__ C,
                  __nv_bfloat16* __restrict__ Chi,
                  __nv_bfloat16* __restrict__ Clo,
                  int M, int Nfull, int relu, int accum,
                  const int* __restrict__ scat,
                  const float* __restrict__ Wd3,
                  const float* __restrict__ bd3,
                  float* __restrict__ out5)
{
    extern __shared__ char smem[];
    const uint32_t sbase = smem_u32(smem);
    const int tid = threadIdx.x;
    const int L   = tid & 31;
    const int wid = tid >> 5;
    const int wm  = wid >> 1;      // 0..3
    const int wn  = wid & 1;       // 0..1
    const int bn0 = blockIdx.x * 128;
    const int bm0 = blockIdx.y * 128;
    const int Ktot = segs.Ktot;

    // ---- staging setup: thread -> (row srow 0..127, half sh 0..1) ----
    const int srow = tid >> 1;
    const int sh   = tid & 1;
    uint32_t soff[4];
#pragma unroll
    for (int i = 0; i < 4; i++) {
        int ch = sh * 4 + i;
        soff[i] = (uint32_t)(srow * 128 + ((ch ^ (srow & 7)) * 16));
    }
    const int arow_g = bm0 + srow;
    const __nv_bfloat16* ah[4];
    const __nv_bfloat16* al[4];
#pragma unroll
    for (int s = 0; s < 4; s++) {
        if (s < segs.n) {
            int gr = 0;
            if (arow_g < M) gr = segs.s[s].g ? segs.s[s].g[arow_g] : arow_g;
            ah[s] = segs.s[s].h + (size_t)gr * segs.s[s].K + sh * 32;
            al[s] = segs.s[s].l + (size_t)gr * segs.s[s].K + sh * 32;
        } else {
            ah[s] = segs.s[0].h;
            al[s] = segs.s[0].l;
        }
    }
    const __nv_bfloat16* bph = Bhi + (size_t)(bn0 + srow) * Ktot + sh * 32;
    const __nv_bfloat16* bpl = Blo + (size_t)(bn0 + srow) * Ktot + sh * 32;

    const int per = Ktot / 64;     // chunks per pass
    const int nch = 3 * per;

    // ---- ldmatrix per-lane address precompute ----
    uint32_t a_rbase[2], b_rbase[4];
    int a_rsw[2], b_rsw[4];
    const int a_csel = L >> 4;
    const int b_csel = (L >> 3) & 1;
#pragma unroll
    for (int mf = 0; mf < 2; mf++) {
        int r = wm * 32 + mf * 16 + ((L >> 3) & 1) * 8 + (L & 7);
        a_rbase[mf] = (uint32_t)(r * 128);
        a_rsw[mf] = r & 7;
    }
#pragma unroll
    for (int nf2 = 0; nf2 < 4; nf2++) {
        int r = wn * 64 + nf2 * 16 + (L >> 4) * 8 + (L & 7);
        b_rbase[nf2] = (uint32_t)(r * 128);
        b_rsw[nf2] = r & 7;
    }

    float acc[2][8][4];
#pragma unroll
    for (int mf = 0; mf < 2; mf++)
#pragma unroll
        for (int nf = 0; nf < 8; nf++)
#pragma unroll
            for (int q = 0; q < 4; q++) acc[mf][nf][q] = 0.0f;

    auto stage = [&](int c) {
        const int bufsel = c & 1;
        const int p  = c / per;
        const int k0 = (c - p * per) * 64;
        int s = 0;
#pragma unroll
        for (int q = 1; q < 4; q++)
            if (k0 >= segs.s[q].off) s = q;   // unused segs: off = Ktot sentinel
        const int lk = k0 - segs.s[s].off;
        const __nv_bfloat16* as = ((p == 2) ? al[s] : ah[s]) + lk;
        const __nv_bfloat16* bs = ((p == 1) ? bpl : bph) + k0;
        const uint32_t ab = sbase + bufsel * 16384;
        const uint32_t bb = sbase + 32768 + bufsel * 16384;
#pragma unroll
        for (int i = 0; i < 4; i++) {
            cp16(ab + soff[i], as + i * 8);
            cp16(bb + soff[i], bs + i * 8);
        }
        CP_COMMIT();
    };

    stage(0);

    for (int c = 0; c < nch; c++) {
        const int buf = c & 1;
        if (c + 1 < nch) { stage(c + 1); CP_WAIT(1); }
        else             { CP_WAIT(0); }
        __syncthreads();

        const uint32_t Ab = sbase + buf * 16384;
        const uint32_t Bb = sbase + 32768 + buf * 16384;
#pragma unroll
        for (int j = 0; j < 4; j++) {
            uint32_t a0[4], a1[4];
            {
                uint32_t ca = (uint32_t)(((2 * j + a_csel) ^ a_rsw[0]) * 16);
                LDSM4(a0[0], a0[1], a0[2], a0[3], Ab + a_rbase[0] + ca);
                uint32_t cb = (uint32_t)(((2 * j + a_csel) ^ a_rsw[1]) * 16);
                LDSM4(a1[0], a1[1], a1[2], a1[3], Ab + a_rbase[1] + cb);
            }
            uint32_t bv[4][4];
#pragma unroll
            for (int nf2 = 0; nf2 < 4; nf2++) {
                uint32_t cb = (uint32_t)(((2 * j + b_csel) ^ b_rsw[nf2]) * 16);
                LDSM4(bv[nf2][0], bv[nf2][1], bv[nf2][2], bv[nf2][3],
                      Bb + b_rbase[nf2] + cb);
            }
#pragma unroll
            for (int nf2 = 0; nf2 < 4; nf2++) {
                MMA16816(acc[0][2 * nf2],     a0, bv[nf2][0], bv[nf2][1]);
                MMA16816(acc[0][2 * nf2 + 1], a0, bv[nf2][2], bv[nf2][3]);
                MMA16816(acc[1][2 * nf2],     a1, bv[nf2][0], bv[nf2][1]);
                MMA16816(acc[1][2 * nf2 + 1], a1, bv[nf2][2], bv[nf2][3]);
            }
        }
        __syncthreads();
    }

    // ---- epilogue ----
    float* Cs = (float*)smem;   // out5 staging (reuse; all threads past last sync)
#pragma unroll
    for (int mf = 0; mf < 2; mf++) {
#pragma unroll
        for (int nf = 0; nf < 8; nf++) {
            const int col = bn0 + wn * 64 + nf * 8 + (L & 3) * 2;
#pragma unroll
            for (int half = 0; half < 2; half++) {
                const int m = bm0 + wm * 32 + mf * 16 + (L >> 2) + half * 8;
                if (m >= M) continue;
                float v0 = acc[mf][nf][half * 2 + 0];
                float v1 = acc[mf][nf][half * 2 + 1];
                if (bias) { v0 += bias[col]; v1 += bias[col + 1]; }
                if (scat) {
                    // fused scatter: agg[scat[m]] += relu(v)
                    v0 = fmaxf(v0, 0.f); v1 = fmaxf(v1, 0.f);
                    float* ap = &C[(size_t)scat[m] * Nfull + col];
                    if (v0 != 0.0f) atomicAdd(ap + 0, v0);
                    if (v1 != 0.0f) atomicAdd(ap + 1, v1);
                    continue;
                }
                const size_t o = (size_t)m * Nfull + col;
                if (C && accum) { v0 += C[o]; v1 += C[o + 1]; }
                if (relu) { v0 = fmaxf(v0, 0.f); v1 = fmaxf(v1, 0.f); }
                if (out5) {
                    Cs[(m - bm0) * 128 + (col - bn0)] = v0;
                    Cs[(m - bm0) * 128 + (col - bn0) + 1] = v1;
                    continue;
                }
                if (C) { C[o] = v0; C[o + 1] = v1; }
                if (Chi) {
                    __nv_bfloat16 h0, l0, h1, l1;
                    bf16_split(v0, h0, l0);
                    bf16_split(v1, h1, l1);
                    Chi[o] = h0; Chi[o + 1] = h1;
                    Clo[o] = l0; Clo[o + 1] = l1;
                }
            }
        }
    }

    // ---- fused final projection (128 -> 5), only when out5 set ----
    if (out5) {
        __syncthreads();
        if (tid < 128) {
            const int m = bm0 + tid;
            if (m < M) {
                const float* row = &Cs[tid * 128];
                float s0 = bd3[0], s1 = bd3[1], s2 = bd3[2], s3 = bd3[3], s4 = bd3[4];
#pragma unroll 8
                for (int k = 0; k < 128; k++) {
                    float x = row[k];
                    const float* w = &Wd3[k * 5];
                    s0 = fmaf(x, w[0], s0);
                    s1 = fmaf(x, w[1], s1);
                    s2 = fmaf(x, w[2], s2);
                    s3 = fmaf(x, w[3], s3);
                    s4 = fmaf(x, w[4], s4);
                }
                float* op = &out5[(size_t)m * 5];
                op[0] = s0; op[1] = s1; op[2] = s2; op[3] = s3; op[4] = s4;
            }
        }
    }
}

// ===========================================================================
// Batched weight transpose + split: W[K,N] fp32 -> Th/Tl [N, ldt] bf16 (padded)
// ===========================================================================
struct WJob { const float* W; int K, N, ldt; __nv_bfloat16* Th; __nv_bfloat16* Tl; };
struct WJobs { WJob j[7]; int n; };

__global__ void wt_conv_all(WJobs jobs)
{
    const WJob jb = jobs.j[blockIdx.z];
    const int n0 = blockIdx.x * 32;
    const int k0 = blockIdx.y * 32;
    if (n0 >= jb.N || k0 >= jb.ldt) return;
    __shared__ float tile[32][33];
    const int tx = threadIdx.x, ty = threadIdx.y;  // 32x8
    for (int i = ty; i < 32; i += 8) {
        int k = k0 + i, n = n0 + tx;
        tile[i][tx] = (k < jb.K && n < jb.N) ? jb.W[(size_t)k * jb.N + n] : 0.0f;
    }
    __syncthreads();
    for (int i = ty; i < 32; i += 8) {
        int n = n0 + i, k = k0 + tx;
        if (n < jb.N && k < jb.ldt) {
            float x = tile[tx][i];
            __nv_bfloat16 hb, lb;
            bf16_split(x, hb, lb);
            jb.Th[(size_t)n * jb.ldt + k] = hb;
            jb.Tl[(size_t)n * jb.ldt + k] = lb;
        }
    }
}

// fp32 -> hi/lo planes; also re-zeroes the source (agg reuse across layers)
__global__ void act_conv_kernel(float* __restrict__ X,
                                __nv_bfloat16* __restrict__ Xh,
                                __nv_bfloat16* __restrict__ Xl, int n4)
{
    int i = blockIdx.x * 256 + threadIdx.x;
    if (i >= n4) return;
    float4 x = ((float4*)X)[i];
    __nv_bfloat16 hh[4], ll[4];
    bf16_split(x.x, hh[0], ll[0]);
    bf16_split(x.y, hh[1], ll[1]);
    bf16_split(x.z, hh[2], ll[2]);
    bf16_split(x.w, hh[3], ll[3]);
    *(uint2*)(Xh + (size_t)i * 4) = *(uint2*)hh;
    *(uint2*)(Xl + (size_t)i * 4) = *(uint2*)ll;
    ((float4*)X)[i] = make_float4(0.f, 0.f, 0.f, 0.f);
}

// ===========================================================================
// Elementwise / small kernels
// ===========================================================================
__global__ void init_node_kernel(const float* __restrict__ h_node,
                                 const int* __restrict__ batch_node,
                                 const int* __restrict__ t,
                                 const float* __restrict__ Wne,
                                 float* __restrict__ hn,
                                 __nv_bfloat16* __restrict__ hn_h,
                                 __nv_bfloat16* __restrict__ hn_l,
                                 __nv_bfloat16* __restrict__ extn_h,
                                 __nv_bfloat16* __restrict__ extn_l,
                                 float* __restrict__ tn_out)
{
    int row = blockIdx.x;
    int c = threadIdx.x;  // 256
    __shared__ float hsh[16];
    __shared__ float tn_s;
    if (c < 16) hsh[c] = h_node[row * 16 + c];
    if (c == 0) tn_s = (float)t[batch_node[row]];
    __syncthreads();
    float tn = tn_s;
    float v;
    if (c < 240) {
        v = 0.f;
#pragma unroll
        for (int k = 0; k < 16; k++) v = fmaf(hsh[k], Wne[k * 240 + c], v);
    } else {
        const float step = 1000.0f / 15.0f;
        float dx = tn - (float)(c - 240) * step;
        v = expf((-0.5f / (step * step)) * dx * dx);
    }
    size_t idx = (size_t)row * 256 + c;
    hn[idx] = v;
    __nv_bfloat16 hb, lb; bf16_split(v, hb, lb);
    hn_h[idx] = hb; hn_l[idx] = lb;
    if (c < 64) {
        float ev = (c == 0) ? tn * (1.0f / 1000.0f) : 0.0f;
        __nv_bfloat16 eh, el; bf16_split(ev, eh, el);
        extn_h[(size_t)row * 64 + c] = eh;
        extn_l[(size_t)row * 64 + c] = el;
    }
    if (c == 0) tn_out[row] = tn;
}

__global__ void init_edge_kernel(const float* __restrict__ h_node,
                                 const float* __restrict__ pos,
                                 const int* __restrict__ ei,
                                 const int* __restrict__ batch_edge,
                                 const int* __restrict__ t,
                                 const float* __restrict__ Wee,
                                 float* __restrict__ he,
                                 __nv_bfloat16* __restrict__ he_h,
                                 __nv_bfloat16* __restrict__ he_l,
                                 __nv_bfloat16* __restrict__ exte_h,
                                 __nv_bfloat16* __restrict__ exte_l,
                                 int E)
{
    int e = blockIdx.x;
    int c = threadIdx.x;  // 128
    __shared__ float hsh[32];
    __shared__ float sh[2];
    int s = ei[e], d = ei[E + e];
    if (c < 16)      hsh[c] = h_node[s * 16 + c];
    else if (c < 32) hsh[c] = h_node[d * 16 + (c - 16)];
    if (c == 0) {
        sh[0] = (float)t[batch_edge[e]];
        float dx = pos[d * 3 + 0] - pos[s * 3 + 0];
        float dy = pos[d * 3 + 1] - pos[s * 3 + 1];
        float dz = pos[d * 3 + 2] - pos[s * 3 + 2];
        sh[1] = sqrtf(dx * dx + dy * dy + dz * dz);
    }
    __syncthreads();
    float te = sh[0], dd = sh[1];
    float v;
    if (c < 112) {
        v = 0.f;
#pragma unroll
        for (int k = 0; k < 32; k++) v = fmaf(hsh[k], Wee[k * 112 + c], v);
    } else {
        const float step = 1000.0f / 15.0f;
        float dx = te - (float)(c - 112) * step;
        v = expf((-0.5f / (step * step)) * dx * dx);
    }
    size_t idx = (size_t)e * 128 + c;
    he[idx] = v;
    __nv_bfloat16 hb, lb; bf16_split(v, hb, lb);
    he_h[idx] = hb; he_l[idx] = lb;
    if (c < 64) {
        float ev = 0.0f;
        if (c < 16) {
            const float step = 10.0f / 15.0f;
            float dx = dd - (float)c * step;
            ev = expf((-0.5f / (step * step)) * dx * dx);
        } else if (c == 16) {
            ev = te * (1.0f / 1000.0f);
        }
        __nv_bfloat16 eh, el; bf16_split(ev, eh, el);
        exte_h[(size_t)e * 64 + c] = eh;
        exte_l[(size_t)e * 64 + c] = el;
    }
}

__global__ void zero_kernel(float* __restrict__ p, int n)
{
    int i = blockIdx.x * 256 + threadIdx.x;
    if (i < n) p[i] = 0.0f;
}

__global__ void sym_kernel(const float* __restrict__ he,
                           __nv_bfloat16* __restrict__ oh,
                           __nv_bfloat16* __restrict__ ol, int nh)
{
    size_t i = (size_t)blockIdx.x * 256 + threadIdx.x;
    if (i >= (size_t)nh * 128) return;
    float v = he[i] + he[i + (size_t)nh * 128];
    __nv_bfloat16 hb, lb; bf16_split(v, hb, lb);
    oh[i] = hb; ol[i] = lb;
}

__global__ void pair_kernel(const float* __restrict__ hn, const int* __restrict__ ei,
                            __nv_bfloat16* __restrict__ oh,
                            __nv_bfloat16* __restrict__ ol, int nh, int E)
{
    size_t i = (size_t)blockIdx.x * 256 + threadIdx.x;
    if (i >= (size_t)nh * 256) return;
    int e = (int)(i >> 8);
    int c = (int)(i & 255);
    int s = ei[e], d = ei[E + e];
    float v = hn[(size_t)s * 256 + c] + hn[(size_t)d * 256 + c];
    __nv_bfloat16 hb, lb; bf16_split(v, hb, lb);
    oh[i] = hb; ol[i] = lb;
}

// ===========================================================================
// Host side
// ===========================================================================
template <typename T>
static T* sym_addr(T* symbol)
{
    void* p = nullptr;
    cudaGetSymbolAddress(&p, (const void*)symbol);
    return (T*)p;
}

static SegList make_segs(int n,
                         const __nv_bfloat16* h0, const __nv_bfloat16* l0, const int* g0, int K0,
                         const __nv_bfloat16* h1 = nullptr, const __nv_bfloat16* l1 = nullptr,
                         const int* g1 = nullptr, int K1 = 0,
                         const __nv_bfloat16* h2 = nullptr, const __nv_bfloat16* l2 = nullptr,
                         const int* g2 = nullptr, int K2 = 0,
                         const __nv_bfloat16* h3 = nullptr, const __nv_bfloat16* l3 = nullptr,
                         const int* g3 = nullptr, int K3 = 0)
{
    SegList sl;
    sl.s[0] = {h0, l0, g0, K0, 0};
    sl.s[1] = {h1, l1, g1, K1, 0};
    sl.s[2] = {h2, l2, g2, K2, 0};
    sl.s[3] = {h3, l3, g3, K3, 0};
    sl.n = n;
    int off = 0;
    for (int i = 0; i < 4; i++) {
        if (i < n) { sl.s[i].off = off; off += sl.s[i].K; }
    }
    sl.Ktot = off;
    for (int i = n; i < 4; i++) sl.s[i].off = off;   // sentinel: never selected
    return sl;
}

static void launch_tgemm(const SegList& segs,
                         const __nv_bfloat16* Bh, const __nv_bfloat16* Bl,
                         const float* bias, float* C,
                         __nv_bfloat16* Ch, __nv_bfloat16* Cl,
                         int M, int Nfull, int relu, int accum,
                         const int* scat = nullptr,
                         const float* Wd3 = nullptr, const float* bd3 = nullptr,
                         float* out5 = nullptr)
{
    dim3 grid(Nfull / 128, (M + 127) / 128);
    tgemm_kernel<<<grid, 256, TG_SMEM_BYTES>>>(segs, Bh, Bl, bias, C, Ch, Cl,
                                               M, Nfull, relu, accum,
                                               scat, Wd3, bd3, out5);
}

extern "C" void kernel_launch(void* const* d_in, const int* in_sizes, int n_in,
                              void* d_out, int out_size)
{
    cudaFuncSetAttribute(tgemm_kernel, cudaFuncAttributeMaxDynamicSharedMemorySize,
                         TG_SMEM_BYTES);

    const float* h_node     = (const float*)d_in[0];
    const float* pos        = (const float*)d_in[1];
    const int*   batch_node = (const int*)  d_in[2];
    const int*   ei         = (const int*)  d_in[3];
    const int*   batch_edge = (const int*)  d_in[4];
    const int*   t          = (const int*)  d_in[5];
    const float* Wne = (const float*)d_in[6];
    const float* Wee = (const float*)d_in[7];
    const float* We1 = (const float*)d_in[8];
    const float* be1 = (const float*)d_in[9];
    const float* We2 = (const float*)d_in[10];
    const float* be2 = (const float*)d_in[11];
    const float* Wm  = (const float*)d_in[12];
    const float* bm  = (const float*)d_in[13];
    const float* Wn1 = (const float*)d_in[14];
    const float* bn1 = (const float*)d_in[15];
    const float* Wn2 = (const float*)d_in[16];
    const float* bn2 = (const float*)d_in[17];
    const float* Wd1 = (const float*)d_in[18];
    const float* bd1 = (const float*)d_in[19];
    const float* Wd2 = (const float*)d_in[20];
    const float* bd2 = (const float*)d_in[21];
    const float* Wd3 = (const float*)d_in[22];
    const float* bd3 = (const float*)d_in[23];

    const int N  = in_sizes[0] / 16;   // 20000
    const int E  = in_sizes[4];        // 200000
    const int nh = E / 2;              // 100000
    const int* src = ei;
    const int* dst = ei + E;

    float* hn  = sym_addr(g_hn);
    float* he  = sym_addr(g_he);
    float* agg = sym_addr(g_agg);
    float* tn  = sym_addr(g_tn);

    __nv_bfloat16 *hn_h = sym_addr(g_hn_h), *hn_l = sym_addr(g_hn_l);
    __nv_bfloat16 *he_h = sym_addr(g_he_h), *he_l = sym_addr(g_he_l);
    __nv_bfloat16 *hide_h = sym_addr(g_hide_h), *hide_l = sym_addr(g_hide_l);
    __nv_bfloat16 *agg_h = sym_addr(g_agg_h), *agg_l = sym_addr(g_agg_l);
    __nv_bfloat16 *hidn_h = sym_addr(g_hidn_h), *hidn_l = sym_addr(g_hidn_l);
    __nv_bfloat16 *exte_h = sym_addr(g_exte_h), *exte_l = sym_addr(g_exte_l);
    __nv_bfloat16 *extn_h = sym_addr(g_extn_h), *extn_l = sym_addr(g_extn_l);
    __nv_bfloat16 *symh = sym_addr(g_sym_h), *syml = sym_addr(g_sym_l);
    __nv_bfloat16 *pair_h = sym_addr(g_pair_h), *pair_l = sym_addr(g_pair_l);
    __nv_bfloat16 *dec1_h = sym_addr(g_dec1_h), *dec1_l = sym_addr(g_dec1_l);

    __nv_bfloat16 *We1t_h = sym_addr(g_We1t_h), *We1t_l = sym_addr(g_We1t_l);
    __nv_bfloat16 *We2t_h = sym_addr(g_We2t_h), *We2t_l = sym_addr(g_We2t_l);
    __nv_bfloat16 *Wmt_h  = sym_addr(g_Wmt_h),  *Wmt_l  = sym_addr(g_Wmt_l);
    __nv_bfloat16 *Wn1t_h = sym_addr(g_Wn1t_h), *Wn1t_l = sym_addr(g_Wn1t_l);
    __nv_bfloat16 *Wn2t_h = sym_addr(g_Wn2t_h), *Wn2t_l = sym_addr(g_Wn2t_l);
    __nv_bfloat16 *Wd1t_h = sym_addr(g_Wd1t_h), *Wd1t_l = sym_addr(g_Wd1t_l);
    __nv_bfloat16 *Wd2t_h = sym_addr(g_Wd2t_h), *Wd2t_l = sym_addr(g_Wd2t_l);

    // --- weight transpose + split: 2 batched launches ---
    {
        WJobs A; A.n = 5;
        A.j[0] = {We1, 657, 128, 704, We1t_h, We1t_l};
        A.j[1] = {We2, 128, 128, 128, We2t_h, We2t_l};
        A.j[2] = {Wm,  384, 256, 384, Wmt_h,  Wmt_l};
        A.j[3] = {Wn1, 513, 256, 576, Wn1t_h, Wn1t_l};
        A.j[4] = {Wn2, 256, 256, 256, Wn2t_h, Wn2t_l};
        for (int q = 5; q < 7; q++) A.j[q] = A.j[0];
        wt_conv_all<<<dim3(8, 22, 5), dim3(32, 8)>>>(A);

        WJobs B; B.n = 7;
        B.j[0] = {We1 + (size_t)657 * 128, 657, 128, 704,
                  We1t_h + (size_t)128 * 704, We1t_l + (size_t)128 * 704};
        B.j[1] = {We2 + (size_t)128 * 128, 128, 128, 128,
                  We2t_h + (size_t)128 * 128, We2t_l + (size_t)128 * 128};
        B.j[2] = {Wm + (size_t)384 * 256, 384, 256, 384,
                  Wmt_h + (size_t)256 * 384, Wmt_l + (size_t)256 * 384};
        B.j[3] = {Wn1 + (size_t)513 * 256, 513, 256, 576,
                  Wn1t_h + (size_t)256 * 576, Wn1t_l + (size_t)256 * 576};
        B.j[4] = {Wn2 + (size_t)256 * 256, 256, 256, 256,
                  Wn2t_h + (size_t)256 * 256, Wn2t_l + (size_t)256 * 256};
        B.j[5] = {Wd1, 384, 128, 384, Wd1t_h, Wd1t_l};
        B.j[6] = {Wd2, 128, 128, 128, Wd2t_h, Wd2t_l};
        wt_conv_all<<<dim3(8, 22, 7), dim3(32, 8)>>>(B);
    }

    // --- embeddings / geometric features (+ ext segments) ---
    init_node_kernel<<<N, 256>>>(h_node, batch_node, t, Wne, hn, hn_h, hn_l,
                                 extn_h, extn_l, tn);
    init_edge_kernel<<<E, 128>>>(h_node, pos, ei, batch_edge, t, Wee,
                                 he, he_h, he_l, exte_h, exte_l, E);
    zero_kernel<<<(N * 256 + 255) / 256, 256>>>(agg, N * 256);

    // --- L = 2 NodeEdgeNet blocks ---
    for (int l = 0; l < 2; l++) {
        const float* be1l = be1 + (size_t)l * 128;
        const float* be2l = be2 + (size_t)l * 128;
        const float* bml  = bm  + (size_t)l * 256;
        const float* bn1l = bn1 + (size_t)l * 256;
        const float* bn2l = bn2 + (size_t)l * 256;

        const __nv_bfloat16* We1th = We1t_h + (size_t)l * 128 * 704;
        const __nv_bfloat16* We1tl = We1t_l + (size_t)l * 128 * 704;
        const __nv_bfloat16* We2th = We2t_h + (size_t)l * 128 * 128;
        const __nv_bfloat16* We2tl = We2t_l + (size_t)l * 128 * 128;
        const __nv_bfloat16* Wmth  = Wmt_h  + (size_t)l * 256 * 384;
        const __nv_bfloat16* Wmtl  = Wmt_l  + (size_t)l * 256 * 384;
        const __nv_bfloat16* Wn1th = Wn1t_h + (size_t)l * 256 * 576;
        const __nv_bfloat16* Wn1tl = Wn1t_l + (size_t)l * 256 * 576;
        const __nv_bfloat16* Wn2th = Wn2t_h + (size_t)l * 256 * 256;
        const __nv_bfloat16* Wn2tl = Wn2t_l + (size_t)l * 256 * 256;

        // hidden_e = relu([h_e | hn[src] | hn[dst] | ext_e] @ We1t^T + be1) -> planes
        launch_tgemm(make_segs(4,
                         he_h, he_l, nullptr, 128,
                         hn_h, hn_l, src,     256,
                         hn_h, hn_l, dst,     256,
                         exte_h, exte_l, nullptr, 64),
                     We1th, We1tl, be1l, nullptr, hide_h, hide_l, E, 128, 1, 0);

        // h_e += hidden_e @ We2 + be2 (residual, fp32) + planes
        launch_tgemm(make_segs(1, hide_h, hide_l, nullptr, 128),
                     We2th, We2tl, be2l, he, he_h, he_l, E, 128, 0, 1);

        // agg[dst] += relu([hn[src] | h_e] @ Wm + bm)  (fused scatter epilogue)
        launch_tgemm(make_segs(2,
                         hn_h, hn_l, src, 256,
                         he_h, he_l, nullptr, 128),
                     Wmth, Wmtl, bml, agg, nullptr, nullptr, E, 256, 1, 0, dst);

        // agg planes + re-zero agg for next layer
        act_conv_kernel<<<(N * 64 + 255) / 256, 256>>>(agg, agg_h, agg_l, N * 64);

        // hidden_n = relu([h_n | agg | ext_n] @ Wn1 + bn1) -> planes
        launch_tgemm(make_segs(3,
                         hn_h, hn_l, nullptr, 256,
                         agg_h, agg_l, nullptr, 256,
                         extn_h, extn_l, nullptr, 64),
                     Wn1th, Wn1tl, bn1l, nullptr, hidn_h, hidn_l, N, 256, 1, 0);

        // h_n += hidden_n @ Wn2 + bn2 (residual, fp32) + planes
        launch_tgemm(make_segs(1, hidn_h, hidn_l, nullptr, 256),
                     Wn2th, Wn2tl, bn2l, hn, hn_h, hn_l, N, 256, 0, 1);
    }

    // --- decode ---
    sym_kernel <<<(int)(((size_t)nh * 128 + 255) / 256), 256>>>(he, symh, syml, nh);
    pair_kernel<<<(int)(((size_t)nh * 256 + 255) / 256), 256>>>(hn, ei, pair_h, pair_l, nh, E);

    // dec1 = relu([sym | pair] @ Wd1 + bd1) -> planes
    launch_tgemm(make_segs(2,
                     symh, syml, nullptr, 128,
                     pair_h, pair_l, nullptr, 256),
                 Wd1t_h, Wd1t_l, bd1, nullptr, dec1_h, dec1_l, nh, 128, 1, 0);

    // out = relu(dec1 @ Wd2 + bd2) @ Wd3 + bd3   (fused final projection)
    launch_tgemm(make_segs(1, dec1_h, dec1_l, nullptr, 128),
                 Wd2t_h, Wd2t_l, bd2, nullptr, nullptr, nullptr, nh, 128, 1, 0,
                 nullptr, Wd3, bd3, (float*)d_out);
}

// round 11
// speedup vs baseline: 2.6040x; 1.3076x over previous
#include <cuda_runtime.h>
#include <cuda_bf16.h>
#include <math.h>
#include <stdint.h>

// ===========================================================================
// BondPredictor: HMMA (mma.sync bf16) GEMMs via bf16x3 split precision.
// Node-space hoisting of linear gather segments (P1/P2/Q/R) + epilogue gathers.
// N=20000 nodes, E=200000 edges, ND=256, ED=128, L=2, NE=5.
// ===========================================================================

#define N_MAX 20000
#define E_MAX 200000
#define NH_MAX (E_MAX / 2)

// ------------------------- fp32 scratch -----------------------------------
__device__ float g_hn [(size_t)N_MAX * 256];
__device__ float g_he [(size_t)E_MAX * 128];
__device__ float g_agg[(size_t)N_MAX * 256];
__device__ float g_P1 [(size_t)N_MAX * 128];   // also reused as R in decode
__device__ float g_P2 [(size_t)N_MAX * 128];
__device__ float g_Q  [(size_t)N_MAX * 256];

// ------------------------- bf16 hi/lo planes (activations) -----------------
__device__ __nv_bfloat16 g_hn_h  [(size_t)N_MAX * 256];
__device__ __nv_bfloat16 g_hn_l  [(size_t)N_MAX * 256];
__device__ __nv_bfloat16 g_he_h  [(size_t)E_MAX * 128];
__device__ __nv_bfloat16 g_he_l  [(size_t)E_MAX * 128];
__device__ __nv_bfloat16 g_hide_h[(size_t)E_MAX * 128];
__device__ __nv_bfloat16 g_hide_l[(size_t)E_MAX * 128];
__device__ __nv_bfloat16 g_agg_h [(size_t)N_MAX * 256];
__device__ __nv_bfloat16 g_agg_l [(size_t)N_MAX * 256];
__device__ __nv_bfloat16 g_hidn_h[(size_t)N_MAX * 256];
__device__ __nv_bfloat16 g_hidn_l[(size_t)N_MAX * 256];
__device__ __nv_bfloat16 g_exte_h[(size_t)E_MAX * 64];
__device__ __nv_bfloat16 g_exte_l[(size_t)E_MAX * 64];
__device__ __nv_bfloat16 g_extn_h[(size_t)N_MAX * 64];
__device__ __nv_bfloat16 g_extn_l[(size_t)N_MAX * 64];
__device__ __nv_bfloat16 g_sym_h [(size_t)NH_MAX * 128];
__device__ __nv_bfloat16 g_sym_l [(size_t)NH_MAX * 128];
__device__ __nv_bfloat16 g_dec1_h[(size_t)NH_MAX * 128];
__device__ __nv_bfloat16 g_dec1_l[(size_t)NH_MAX * 128];

// ------------------------- transposed+split weights [N, ld] ----------------
__device__ __nv_bfloat16 g_We1t_h[2 * 128 * 704];
__device__ __nv_bfloat16 g_We1t_l[2 * 128 * 704];
__device__ __nv_bfloat16 g_We2t_h[2 * 128 * 128];
__device__ __nv_bfloat16 g_We2t_l[2 * 128 * 128];
__device__ __nv_bfloat16 g_Wmt_h [2 * 256 * 384];
__device__ __nv_bfloat16 g_Wmt_l [2 * 256 * 384];
__device__ __nv_bfloat16 g_Wn1t_h[2 * 256 * 576];
__device__ __nv_bfloat16 g_Wn1t_l[2 * 256 * 576];
__device__ __nv_bfloat16 g_Wn2t_h[2 * 256 * 256];
__device__ __nv_bfloat16 g_Wn2t_l[2 * 256 * 256];
__device__ __nv_bfloat16 g_Wd1t_h[128 * 384];
__device__ __nv_bfloat16 g_Wd1t_l[128 * 384];
__device__ __nv_bfloat16 g_Wd2t_h[128 * 128];
__device__ __nv_bfloat16 g_Wd2t_l[128 * 128];

// ===========================================================================
// PTX helpers (sm_80-era: valid on plain sm_103 target)
// ===========================================================================
__device__ __forceinline__ uint32_t smem_u32(const void* p) {
    uint32_t a;
    asm("{ .reg .u64 t; cvta.to.shared.u64 t, %1; cvt.u32.u64 %0, t; }"
        : "=r"(a) : "l"(p));
    return a;
}
__device__ __forceinline__ void cp16(uint32_t dst, const void* src) {
    asm volatile("cp.async.cg.shared.global [%0], [%1], 16;" :: "r"(dst), "l"(src));
}
#define CP_COMMIT()  asm volatile("cp.async.commit_group;" ::: "memory")
#define CP_WAIT(n)   asm volatile("cp.async.wait_group %0;" :: "n"(n) : "memory")

#define LDSM4(r0, r1, r2, r3, addr) \
    asm volatile("ldmatrix.sync.aligned.m8n8.x4.shared.b16 {%0,%1,%2,%3}, [%4];" \
                 : "=r"(r0), "=r"(r1), "=r"(r2), "=r"(r3) : "r"(addr))

#define MMA16816(d, a, b0, b1) \
    asm volatile("mma.sync.aligned.m16n8k16.row.col.f32.bf16.bf16.f32 " \
                 "{%0,%1,%2,%3},{%4,%5,%6,%7},{%8,%9},{%0,%1,%2,%3};" \
                 : "+f"((d)[0]), "+f"((d)[1]), "+f"((d)[2]), "+f"((d)[3]) \
                 : "r"((a)[0]), "r"((a)[1]), "r"((a)[2]), "r"((a)[3]), \
                   "r"(b0), "r"(b1))

__device__ __forceinline__ void bf16_split(float x, __nv_bfloat16& h, __nv_bfloat16& l) {
    h = __float2bfloat16(x);
    l = __float2bfloat16(x - __bfloat162float(h));
}

// ===========================================================================
// Multi-segment HMMA GEMM (bf16x3) with:
//   - per-segment B column offset (boff) into a [Nout, ldb] weight
//   - epilogue gather-adds (G1/G2: fp32 rows indexed by gi[m], stride gs, +go)
//   - epilogue modes: scatter-atomic / fused 128->5 projection / fp32 C /
//     bf16 hi-lo planes
// ===========================================================================
#define TG_SMEM_BYTES 65536

struct Seg { const __nv_bfloat16* h; const __nv_bfloat16* l; const int* g;
             int K; int off; int boff; };
struct SegList { Seg s[4]; int n; int Ktot; };
struct GAdd { const float* G1; const int* gi1; int gs1, go1;
              const float* G2; const int* gi2; int gs2, go2; };

__global__ __launch_bounds__(256)
void tgemm_kernel(SegList segs,
                  const __nv_bfloat16* __restrict__ Bhi,   // [Nout, ldb]
                  const __nv_bfloat16* __restrict__ Blo,
                  int ldb,
                  GAdd ga,
                  const float* __restrict__ bias,
                  float* __restrict__ C,
                  __nv_bfloat16* __restrict__ Chi,
                  __nv_bfloat16* __restrict__ Clo,
                  int M, int Nfull, int relu, int accum,
                  const int* __restrict__ scat,
                  const float* __restrict__ Wd3,
                  const float* __restrict__ bd3,
                  float* __restrict__ out5)
{
    extern __shared__ char smem[];
    const uint32_t sbase = smem_u32(smem);
    const int tid = threadIdx.x;
    const int L   = tid & 31;
    const int wid = tid >> 5;
    const int wm  = wid >> 1;      // 0..3
    const int wn  = wid & 1;       // 0..1
    const int bn0 = blockIdx.x * 128;
    const int bm0 = blockIdx.y * 128;
    const int Ktot = segs.Ktot;

    // ---- staging setup: thread -> (row srow 0..127, half sh 0..1) ----
    const int srow = tid >> 1;
    const int sh   = tid & 1;
    uint32_t soff[4];
#pragma unroll
    for (int i = 0; i < 4; i++) {
        int ch = sh * 4 + i;
        soff[i] = (uint32_t)(srow * 128 + ((ch ^ (srow & 7)) * 16));
    }
    const int arow_g = bm0 + srow;
    const __nv_bfloat16* ah[4];
    const __nv_bfloat16* al[4];
#pragma unroll
    for (int s = 0; s < 4; s++) {
        if (s < segs.n) {
            int gr = 0;
            if (arow_g < M) gr = segs.s[s].g ? segs.s[s].g[arow_g] : arow_g;
            ah[s] = segs.s[s].h + (size_t)gr * segs.s[s].K + sh * 32;
            al[s] = segs.s[s].l + (size_t)gr * segs.s[s].K + sh * 32;
        } else {
            ah[s] = segs.s[0].h;
            al[s] = segs.s[0].l;
        }
    }
    const size_t brow = (size_t)(bn0 + srow) * ldb + sh * 32;

    const int per = Ktot / 64;     // chunks per pass
    const int nch = 3 * per;

    // ---- ldmatrix per-lane address precompute ----
    uint32_t a_rbase[2], b_rbase[4];
    int a_rsw[2], b_rsw[4];
    const int a_csel = L >> 4;
    const int b_csel = (L >> 3) & 1;
#pragma unroll
    for (int mf = 0; mf < 2; mf++) {
        int r = wm * 32 + mf * 16 + ((L >> 3) & 1) * 8 + (L & 7);
        a_rbase[mf] = (uint32_t)(r * 128);
        a_rsw[mf] = r & 7;
    }
#pragma unroll
    for (int nf2 = 0; nf2 < 4; nf2++) {
        int r = wn * 64 + nf2 * 16 + (L >> 4) * 8 + (L & 7);
        b_rbase[nf2] = (uint32_t)(r * 128);
        b_rsw[nf2] = r & 7;
    }

    float acc[2][8][4];
#pragma unroll
    for (int mf = 0; mf < 2; mf++)
#pragma unroll
        for (int nf = 0; nf < 8; nf++)
#pragma unroll
            for (int q = 0; q < 4; q++) acc[mf][nf][q] = 0.0f;

    auto stage = [&](int c) {
        const int bufsel = c & 1;
        const int p  = c / per;
        const int k0 = (c - p * per) * 64;
        int s = 0;
#pragma unroll
        for (int q = 1; q < 4; q++)
            if (k0 >= segs.s[q].off) s = q;   // unused segs: off = Ktot sentinel
        const int lk = k0 - segs.s[s].off;
        const __nv_bfloat16* as = ((p == 2) ? al[s] : ah[s]) + lk;
        const __nv_bfloat16* Bb0 = (p == 1) ? Blo : Bhi;
        const __nv_bfloat16* bs = Bb0 + brow + segs.s[s].boff + lk;
        const uint32_t ab = sbase + bufsel * 16384;
        const uint32_t bb = sbase + 32768 + bufsel * 16384;
#pragma unroll
        for (int i = 0; i < 4; i++) {
            cp16(ab + soff[i], as + i * 8);
            cp16(bb + soff[i], bs + i * 8);
        }
        CP_COMMIT();
    };

    stage(0);

    for (int c = 0; c < nch; c++) {
        const int buf = c & 1;
        if (c + 1 < nch) { stage(c + 1); CP_WAIT(1); }
        else             { CP_WAIT(0); }
        __syncthreads();

        const uint32_t Ab = sbase + buf * 16384;
        const uint32_t Bb = sbase + 32768 + buf * 16384;
#pragma unroll
        for (int j = 0; j < 4; j++) {
            uint32_t a0[4], a1[4];
            {
                uint32_t ca = (uint32_t)(((2 * j + a_csel) ^ a_rsw[0]) * 16);
                LDSM4(a0[0], a0[1], a0[2], a0[3], Ab + a_rbase[0] + ca);
                uint32_t cb = (uint32_t)(((2 * j + a_csel) ^ a_rsw[1]) * 16);
                LDSM4(a1[0], a1[1], a1[2], a1[3], Ab + a_rbase[1] + cb);
            }
            uint32_t bv[4][4];
#pragma unroll
            for (int nf2 = 0; nf2 < 4; nf2++) {
                uint32_t cb = (uint32_t)(((2 * j + b_csel) ^ b_rsw[nf2]) * 16);
                LDSM4(bv[nf2][0], bv[nf2][1], bv[nf2][2], bv[nf2][3],
                      Bb + b_rbase[nf2] + cb);
            }
#pragma unroll
            for (int nf2 = 0; nf2 < 4; nf2++) {
                MMA16816(acc[0][2 * nf2],     a0, bv[nf2][0], bv[nf2][1]);
                MMA16816(acc[0][2 * nf2 + 1], a0, bv[nf2][2], bv[nf2][3]);
                MMA16816(acc[1][2 * nf2],     a1, bv[nf2][0], bv[nf2][1]);
                MMA16816(acc[1][2 * nf2 + 1], a1, bv[nf2][2], bv[nf2][3]);
            }
        }
        __syncthreads();
    }

    // ---- epilogue ----
    float* Cs = (float*)smem;   // out5 staging (reuse; all threads past last sync)
#pragma unroll
    for (int mf = 0; mf < 2; mf++) {
#pragma unroll
        for (int half = 0; half < 2; half++) {
            const int m = bm0 + wm * 32 + mf * 16 + (L >> 2) + half * 8;
            if (m >= M) continue;
            const float* g1r = ga.G1 ? ga.G1 + (size_t)ga.gi1[m] * ga.gs1 + ga.go1
                                     : nullptr;
            const float* g2r = ga.G2 ? ga.G2 + (size_t)ga.gi2[m] * ga.gs2 + ga.go2
                                     : nullptr;
            float* srowp = scat ? &C[(size_t)scat[m] * Nfull] : nullptr;
#pragma unroll
            for (int nf = 0; nf < 8; nf++) {
                const int col = bn0 + wn * 64 + nf * 8 + (L & 3) * 2;
                float v0 = acc[mf][nf][half * 2 + 0];
                float v1 = acc[mf][nf][half * 2 + 1];
                if (g1r) { v0 += g1r[col]; v1 += g1r[col + 1]; }
                if (g2r) { v0 += g2r[col]; v1 += g2r[col + 1]; }
                if (bias) { v0 += bias[col]; v1 += bias[col + 1]; }
                if (scat) {
                    v0 = fmaxf(v0, 0.f); v1 = fmaxf(v1, 0.f);
                    if (v0 != 0.0f) atomicAdd(srowp + col, v0);
                    if (v1 != 0.0f) atomicAdd(srowp + col + 1, v1);
                    continue;
                }
                const size_t o = (size_t)m * Nfull + col;
                if (C && accum) { v0 += C[o]; v1 += C[o + 1]; }
                if (relu) { v0 = fmaxf(v0, 0.f); v1 = fmaxf(v1, 0.f); }
                if (out5) {
                    Cs[(m - bm0) * 128 + (col - bn0)] = v0;
                    Cs[(m - bm0) * 128 + (col - bn0) + 1] = v1;
                    continue;
                }
                if (C) { C[o] = v0; C[o + 1] = v1; }
                if (Chi) {
                    __nv_bfloat16 h0, l0, h1, l1;
                    bf16_split(v0, h0, l0);
                    bf16_split(v1, h1, l1);
                    Chi[o] = h0; Chi[o + 1] = h1;
                    Clo[o] = l0; Clo[o + 1] = l1;
                }
            }
        }
    }

    // ---- fused final projection (128 -> 5), only when out5 set ----
    if (out5) {
        __syncthreads();
        if (tid < 128) {
            const int m = bm0 + tid;
            if (m < M) {
                const float* row = &Cs[tid * 128];
                float s0 = bd3[0], s1 = bd3[1], s2 = bd3[2], s3 = bd3[3], s4 = bd3[4];
#pragma unroll 8
                for (int k = 0; k < 128; k++) {
                    float x = row[k];
                    const float* w = &Wd3[k * 5];
                    s0 = fmaf(x, w[0], s0);
                    s1 = fmaf(x, w[1], s1);
                    s2 = fmaf(x, w[2], s2);
                    s3 = fmaf(x, w[3], s3);
                    s4 = fmaf(x, w[4], s4);
                }
                float* op = &out5[(size_t)m * 5];
                op[0] = s0; op[1] = s1; op[2] = s2; op[3] = s3; op[4] = s4;
            }
        }
    }
}

// ===========================================================================
// Batched weight transpose + split: W[K,N] fp32 -> Th/Tl [N, ldt] bf16 (padded)
// ===========================================================================
struct WJob { const float* W; int K, N, ldt; __nv_bfloat16* Th; __nv_bfloat16* Tl; };
struct WJobs { WJob j[7]; int n; };

__global__ void wt_conv_all(WJobs jobs)
{
    const WJob jb = jobs.j[blockIdx.z];
    const int n0 = blockIdx.x * 32;
    const int k0 = blockIdx.y * 32;
    if (n0 >= jb.N || k0 >= jb.ldt) return;
    __shared__ float tile[32][33];
    const int tx = threadIdx.x, ty = threadIdx.y;  // 32x8
    for (int i = ty; i < 32; i += 8) {
        int k = k0 + i, n = n0 + tx;
        tile[i][tx] = (k < jb.K && n < jb.N) ? jb.W[(size_t)k * jb.N + n] : 0.0f;
    }
    __syncthreads();
    for (int i = ty; i < 32; i += 8) {
        int n = n0 + i, k = k0 + tx;
        if (n < jb.N && k < jb.ldt) {
            float x = tile[tx][i];
            __nv_bfloat16 hb, lb;
            bf16_split(x, hb, lb);
            jb.Th[(size_t)n * jb.ldt + k] = hb;
            jb.Tl[(size_t)n * jb.ldt + k] = lb;
        }
    }
}

// fp32 -> hi/lo planes; also re-zeroes the source (agg reuse across layers)
__global__ void act_conv_kernel(float* __restrict__ X,
                                __nv_bfloat16* __restrict__ Xh,
                                __nv_bfloat16* __restrict__ Xl, int n4)
{
    int i = blockIdx.x * 256 + threadIdx.x;
    if (i >= n4) return;
    float4 x = ((float4*)X)[i];
    __nv_bfloat16 hh[4], ll[4];
    bf16_split(x.x, hh[0], ll[0]);
    bf16_split(x.y, hh[1], ll[1]);
    bf16_split(x.z, hh[2], ll[2]);
    bf16_split(x.w, hh[3], ll[3]);
    *(uint2*)(Xh + (size_t)i * 4) = *(uint2*)hh;
    *(uint2*)(Xl + (size_t)i * 4) = *(uint2*)ll;
    ((float4*)X)[i] = make_float4(0.f, 0.f, 0.f, 0.f);
}

// ===========================================================================
// Elementwise / small kernels
// ===========================================================================
__global__ void init_node_kernel(const float* __restrict__ h_node,
                                 const int* __restrict__ batch_node,
                                 const int* __restrict__ t,
                                 const float* __restrict__ Wne,
                                 float* __restrict__ hn,
                                 __nv_bfloat16* __restrict__ hn_h,
                                 __nv_bfloat16* __restrict__ hn_l,
                                 __nv_bfloat16* __restrict__ extn_h,
                                 __nv_bfloat16* __restrict__ extn_l)
{
    int row = blockIdx.x;
    int c = threadIdx.x;  // 256
    __shared__ float hsh[16];
    __shared__ float tn_s;
    if (c < 16) hsh[c] = h_node[row * 16 + c];
    if (c == 0) tn_s = (float)t[batch_node[row]];
    __syncthreads();
    float tn = tn_s;
    float v;
    if (c < 240) {
        v = 0.f;
#pragma unroll
        for (int k = 0; k < 16; k++) v = fmaf(hsh[k], Wne[k * 240 + c], v);
    } else {
        const float step = 1000.0f / 15.0f;
        float dx = tn - (float)(c - 240) * step;
        v = expf((-0.5f / (step * step)) * dx * dx);
    }
    size_t idx = (size_t)row * 256 + c;
    hn[idx] = v;
    __nv_bfloat16 hb, lb; bf16_split(v, hb, lb);
    hn_h[idx] = hb; hn_l[idx] = lb;
    if (c < 64) {
        float ev = (c == 0) ? tn * (1.0f / 1000.0f) : 0.0f;
        __nv_bfloat16 eh, el; bf16_split(ev, eh, el);
        extn_h[(size_t)row * 64 + c] = eh;
        extn_l[(size_t)row * 64 + c] = el;
    }
}

// warp-per-edge: block = 256 threads = 8 edges. Vectorized 4-col processing.
__global__ void init_edge_kernel(const float* __restrict__ h_node,
                                 const float* __restrict__ pos,
                                 const int* __restrict__ ei,
                                 const int* __restrict__ batch_edge,
                                 const int* __restrict__ t,
                                 const float* __restrict__ Wee,
                                 float* __restrict__ he,
                                 __nv_bfloat16* __restrict__ he_h,
                                 __nv_bfloat16* __restrict__ he_l,
                                 __nv_bfloat16* __restrict__ exte_h,
                                 __nv_bfloat16* __restrict__ exte_l,
                                 int E)
{
    const int e = blockIdx.x * 8 + (threadIdx.x >> 5);
    const int L = threadIdx.x & 31;
    if (e >= E) return;
    const int s = ei[e], d = ei[E + e];

    // lane-held h value: lanes 0-15 = h_node[s], 16-31 = h_node[d]
    const float hv = (L < 16) ? h_node[s * 16 + L] : h_node[d * 16 + (L - 16)];
    const float te = (float)t[batch_edge[e]];
    const float dx = pos[d * 3 + 0] - pos[s * 3 + 0];
    const float dy = pos[d * 3 + 1] - pos[s * 3 + 1];
    const float dz = pos[d * 3 + 2] - pos[s * 3 + 2];
    const float dd = sqrtf(dx * dx + dy * dy + dz * dz);

    const int c0 = L * 4;                 // this lane's 4 columns
    float v[4] = {0.f, 0.f, 0.f, 0.f};
    const bool dotlane = (c0 < 112);
#pragma unroll
    for (int k = 0; k < 32; k++) {
        float x = __shfl_sync(0xffffffffu, hv, k);
        if (dotlane) {
            float4 w = *(const float4*)&Wee[k * 112 + c0];
            v[0] = fmaf(x, w.x, v[0]);
            v[1] = fmaf(x, w.y, v[1]);
            v[2] = fmaf(x, w.z, v[2]);
            v[3] = fmaf(x, w.w, v[3]);
        }
    }
    if (!dotlane) {
        const float step = 1000.0f / 15.0f;
        const float cf = -0.5f / (step * step);
#pragma unroll
        for (int i = 0; i < 4; i++) {
            float dt = te - (float)(c0 + i - 112) * step;
            v[i] = expf(cf * dt * dt);
        }
    }
    const size_t idx = (size_t)e * 128 + c0;
    *(float4*)&he[idx] = make_float4(v[0], v[1], v[2], v[3]);
    __nv_bfloat16 hh[4], ll[4];
#pragma unroll
    for (int i = 0; i < 4; i++) bf16_split(v[i], hh[i], ll[i]);
    *(uint2*)&he_h[idx] = *(uint2*)hh;
    *(uint2*)&he_l[idx] = *(uint2*)ll;

    if (L < 16) {
        float ev[4];
#pragma unroll
        for (int i = 0; i < 4; i++) {
            int c = c0 + i;
            if (c < 16) {
                const float step = 10.0f / 15.0f;
                float dv = dd - (float)c * step;
                ev[i] = expf((-0.5f / (step * step)) * dv * dv);
            } else if (c == 16) {
                ev[i] = te * (1.0f / 1000.0f);
            } else {
                ev[i] = 0.0f;
            }
        }
        __nv_bfloat16 eh[4], el[4];
#pragma unroll
        for (int i = 0; i < 4; i++) bf16_split(ev[i], eh[i], el[i]);
        const size_t eidx = (size_t)e * 64 + c0;
        *(uint2*)&exte_h[eidx] = *(uint2*)eh;
        *(uint2*)&exte_l[eidx] = *(uint2*)el;
    }
}

__global__ void zero_kernel(float* __restrict__ p, int n)
{
    int i = blockIdx.x * 256 + threadIdx.x;
    if (i < n) p[i] = 0.0f;
}

__global__ void sym_kernel(const float* __restrict__ he,
                           __nv_bfloat16* __restrict__ oh,
                           __nv_bfloat16* __restrict__ ol, int nh)
{
    size_t i = (size_t)blockIdx.x * 256 + threadIdx.x;
    if (i >= (size_t)nh * 128) return;
    float v = he[i] + he[i + (size_t)nh * 128];
    __nv_bfloat16 hb, lb; bf16_split(v, hb, lb);
    oh[i] = hb; ol[i] = lb;
}

// ===========================================================================
// Host side
// ===========================================================================
template <typename T>
static T* sym_addr(T* symbol)
{
    void* p = nullptr;
    cudaGetSymbolAddress(&p, (const void*)symbol);
    return (T*)p;
}

static SegList make_segs(int n,
                         const __nv_bfloat16* h0, const __nv_bfloat16* l0, const int* g0, int K0,
                         const __nv_bfloat16* h1 = nullptr, const __nv_bfloat16* l1 = nullptr,
                         const int* g1 = nullptr, int K1 = 0,
                         const __nv_bfloat16* h2 = nullptr, const __nv_bfloat16* l2 = nullptr,
                         const int* g2 = nullptr, int K2 = 0)
{
    SegList sl;
    sl.s[0] = {h0, l0, g0, K0, 0, 0};
    sl.s[1] = {h1, l1, g1, K1, 0, 0};
    sl.s[2] = {h2, l2, g2, K2, 0, 0};
    sl.s[3] = {h0, l0, nullptr, K0, 0, 0};
    sl.n = n;
    int off = 0;
    for (int i = 0; i < 3; i++) {
        if (i < n) { sl.s[i].off = off; sl.s[i].boff = off; off += sl.s[i].K; }
    }
    sl.Ktot = off;
    for (int i = n; i < 4; i++) sl.s[i].off = off;   // sentinel: never selected
    return sl;
}

static GAdd make_gadd(const float* G1 = nullptr, const int* gi1 = nullptr,
                      int gs1 = 0, int go1 = 0,
                      const float* G2 = nullptr, const int* gi2 = nullptr,
                      int gs2 = 0, int go2 = 0)
{
    return GAdd{G1, gi1, gs1, go1, G2, gi2, gs2, go2};
}

static void launch_tgemm(const SegList& segs,
                         const __nv_bfloat16* Bh, const __nv_bfloat16* Bl, int ldb,
                         const GAdd& ga,
                         const float* bias, float* C,
                         __nv_bfloat16* Ch, __nv_bfloat16* Cl,
                         int M, int Nfull, int relu, int accum,
                         const int* scat = nullptr,
                         const float* Wd3 = nullptr, const float* bd3 = nullptr,
                         float* out5 = nullptr)
{
    dim3 grid(Nfull / 128, (M + 127) / 128);
    tgemm_kernel<<<grid, 256, TG_SMEM_BYTES>>>(segs, Bh, Bl, ldb, ga, bias,
                                               C, Ch, Cl, M, Nfull, relu, accum,
                                               scat, Wd3, bd3, out5);
}

extern "C" void kernel_launch(void* const* d_in, const int* in_sizes, int n_in,
                              void* d_out, int out_size)
{
    cudaFuncSetAttribute(tgemm_kernel, cudaFuncAttributeMaxDynamicSharedMemorySize,
                         TG_SMEM_BYTES);

    const float* h_node     = (const float*)d_in[0];
    const float* pos        = (const float*)d_in[1];
    const int*   batch_node = (const int*)  d_in[2];
    const int*   ei         = (const int*)  d_in[3];
    const int*   batch_edge = (const int*)  d_in[4];
    const int*   t          = (const int*)  d_in[5];
    const float* Wne = (const float*)d_in[6];
    const float* Wee = (const float*)d_in[7];
    const float* We1 = (const float*)d_in[8];
    const float* be1 = (const float*)d_in[9];
    const float* We2 = (const float*)d_in[10];
    const float* be2 = (const float*)d_in[11];
    const float* Wm  = (const float*)d_in[12];
    const float* bm  = (const float*)d_in[13];
    const float* Wn1 = (const float*)d_in[14];
    const float* bn1 = (const float*)d_in[15];
    const float* Wn2 = (const float*)d_in[16];
    const float* bn2 = (const float*)d_in[17];
    const float* Wd1 = (const float*)d_in[18];
    const float* bd1 = (const float*)d_in[19];
    const float* Wd2 = (const float*)d_in[20];
    const float* bd2 = (const float*)d_in[21];
    const float* Wd3 = (const float*)d_in[22];
    const float* bd3 = (const float*)d_in[23];

    const int N  = in_sizes[0] / 16;   // 20000
    const int E  = in_sizes[4];        // 200000
    const int nh = E / 2;              // 100000
    const int* src = ei;
    const int* dst = ei + E;

    float* hn  = sym_addr(g_hn);
    float* he  = sym_addr(g_he);
    float* agg = sym_addr(g_agg);
    float* P1  = sym_addr(g_P1);
    float* P2  = sym_addr(g_P2);
    float* Q   = sym_addr(g_Q);
    float* R   = P1;   // decode reuse

    __nv_bfloat16 *hn_h = sym_addr(g_hn_h), *hn_l = sym_addr(g_hn_l);
    __nv_bfloat16 *he_h = sym_addr(g_he_h), *he_l = sym_addr(g_he_l);
    __nv_bfloat16 *hide_h = sym_addr(g_hide_h), *hide_l = sym_addr(g_hide_l);
    __nv_bfloat16 *agg_h = sym_addr(g_agg_h), *agg_l = sym_addr(g_agg_l);
    __nv_bfloat16 *hidn_h = sym_addr(g_hidn_h), *hidn_l = sym_addr(g_hidn_l);
    __nv_bfloat16 *exte_h = sym_addr(g_exte_h), *exte_l = sym_addr(g_exte_l);
    __nv_bfloat16 *extn_h = sym_addr(g_extn_h), *extn_l = sym_addr(g_extn_l);
    __nv_bfloat16 *symh = sym_addr(g_sym_h), *syml = sym_addr(g_sym_l);
    __nv_bfloat16 *dec1_h = sym_addr(g_dec1_h), *dec1_l = sym_addr(g_dec1_l);

    __nv_bfloat16 *We1t_h = sym_addr(g_We1t_h), *We1t_l = sym_addr(g_We1t_l);
    __nv_bfloat16 *We2t_h = sym_addr(g_We2t_h), *We2t_l = sym_addr(g_We2t_l);
    __nv_bfloat16 *Wmt_h  = sym_addr(g_Wmt_h),  *Wmt_l  = sym_addr(g_Wmt_l);
    __nv_bfloat16 *Wn1t_h = sym_addr(g_Wn1t_h), *Wn1t_l = sym_addr(g_Wn1t_l);
    __nv_bfloat16 *Wn2t_h = sym_addr(g_Wn2t_h), *Wn2t_l = sym_addr(g_Wn2t_l);
    __nv_bfloat16 *Wd1t_h = sym_addr(g_Wd1t_h), *Wd1t_l = sym_addr(g_Wd1t_l);
    __nv_bfloat16 *Wd2t_h = sym_addr(g_Wd2t_h), *Wd2t_l = sym_addr(g_Wd2t_l);

    // --- weight transpose + split: 2 batched launches ---
    {
        WJobs A; A.n = 5;
        A.j[0] = {We1, 657, 128, 704, We1t_h, We1t_l};
        A.j[1] = {We2, 128, 128, 128, We2t_h, We2t_l};
        A.j[2] = {Wm,  384, 256, 384, Wmt_h,  Wmt_l};
        A.j[3] = {Wn1, 513, 256, 576, Wn1t_h, Wn1t_l};
        A.j[4] = {Wn2, 256, 256, 256, Wn2t_h, Wn2t_l};
        for (int q = 5; q < 7; q++) A.j[q] = A.j[0];
        wt_conv_all<<<dim3(8, 22, 5), dim3(32, 8)>>>(A);

        WJobs B; B.n = 7;
        B.j[0] = {We1 + (size_t)657 * 128, 657, 128, 704,
                  We1t_h + (size_t)128 * 704, We1t_l + (size_t)128 * 704};
        B.j[1] = {We2 + (size_t)128 * 128, 128, 128, 128,
                  We2t_h + (size_t)128 * 128, We2t_l + (size_t)128 * 128};
        B.j[2] = {Wm + (size_t)384 * 256, 384, 256, 384,
                  Wmt_h + (size_t)256 * 384, Wmt_l + (size_t)256 * 384};
        B.j[3] = {Wn1 + (size_t)513 * 256, 513, 256, 576,
                  Wn1t_h + (size_t)256 * 576, Wn1t_l + (size_t)256 * 576};
        B.j[4] = {Wn2 + (size_t)256 * 256, 256, 256, 256,
                  Wn2t_h + (size_t)256 * 256, Wn2t_l + (size_t)256 * 256};
        B.j[5] = {Wd1, 384, 128, 384, Wd1t_h, Wd1t_l};
        B.j[6] = {Wd2, 128, 128, 128, Wd2t_h, Wd2t_l};
        wt_conv_all<<<dim3(8, 22, 7), dim3(32, 8)>>>(B);
    }

    // --- embeddings / geometric features (+ ext segments) ---
    init_node_kernel<<<N, 256>>>(h_node, batch_node, t, Wne, hn, hn_h, hn_l,
                                 extn_h, extn_l);
    init_edge_kernel<<<(E + 7) / 8, 256>>>(h_node, pos, ei, batch_edge, t, Wee,
                                           he, he_h, he_l, exte_h, exte_l, E);
    zero_kernel<<<(N * 256 + 255) / 256, 256>>>(agg, N * 256);

    const GAdd noG = make_gadd();

    // --- L = 2 NodeEdgeNet blocks ---
    for (int l = 0; l < 2; l++) {
        const float* be1l = be1 + (size_t)l * 128;
        const float* be2l = be2 + (size_t)l * 128;
        const float* bml  = bm  + (size_t)l * 256;
        const float* bn1l = bn1 + (size_t)l * 256;
        const float* bn2l = bn2 + (size_t)l * 256;

        const __nv_bfloat16* We1th = We1t_h + (size_t)l * 128 * 704;
        const __nv_bfloat16* We1tl = We1t_l + (size_t)l * 128 * 704;
        const __nv_bfloat16* We2th = We2t_h + (size_t)l * 128 * 128;
        const __nv_bfloat16* We2tl = We2t_l + (size_t)l * 128 * 128;
        const __nv_bfloat16* Wmth  = Wmt_h  + (size_t)l * 256 * 384;
        const __nv_bfloat16* Wmtl  = Wmt_l  + (size_t)l * 256 * 384;
        const __nv_bfloat16* Wn1th = Wn1t_h + (size_t)l * 256 * 576;
        const __nv_bfloat16* Wn1tl = Wn1t_l + (size_t)l * 256 * 576;
        const __nv_bfloat16* Wn2th = Wn2t_h + (size_t)l * 256 * 256;
        const __nv_bfloat16* Wn2tl = Wn2t_l + (size_t)l * 256 * 256;

        // P1 = hn @ We1[128:384], P2 = hn @ We1[384:640]   (node space, fp32)
        {
            SegList sp = make_segs(1, hn_h, hn_l, nullptr, 256);
            sp.s[0].boff = 128;
            launch_tgemm(sp, We1th, We1tl, 704, noG, nullptr, P1, nullptr, nullptr,
                         N, 128, 0, 0);
            sp.s[0].boff = 384;
            launch_tgemm(sp, We1th, We1tl, 704, noG, nullptr, P2, nullptr, nullptr,
                         N, 128, 0, 0);
        }

        // hidden_e = relu(he@W0 + ext@W3 + P1[src] + P2[dst] + be1) -> planes
        {
            SegList se = make_segs(2,
                                   he_h, he_l, nullptr, 128,
                                   exte_h, exte_l, nullptr, 64);
            se.s[1].boff = 640;   // ext maps to We1 rows 640..704
            launch_tgemm(se, We1th, We1tl, 704,
                         make_gadd(P1, src, 128, 0, P2, dst, 128, 0),
                         be1l, nullptr, hide_h, hide_l, E, 128, 1, 0);
        }

        // h_e += hidden_e @ We2 + be2 (residual, fp32) + planes
        launch_tgemm(make_segs(1, hide_h, hide_l, nullptr, 128),
                     We2th, We2tl, 128, noG, be2l, he, he_h, he_l, E, 128, 0, 1);

        // Q = hn @ Wm[0:256]   (node space, fp32, 256-wide)
        launch_tgemm(make_segs(1, hn_h, hn_l, nullptr, 256),
                     Wmth, Wmtl, 384, noG, nullptr, Q, nullptr, nullptr,
                     N, 256, 0, 0);

        // agg[dst] += relu(he@Wm[256:384] + Q[src] + bm)  (fused scatter)
        {
            SegList sm = make_segs(1, he_h, he_l, nullptr, 128);
            sm.s[0].boff = 256;
            launch_tgemm(sm, Wmth, Wmtl, 384,
                         make_gadd(Q, src, 256, 0),
                         bml, agg, nullptr, nullptr, E, 256, 1, 0, dst);
        }

        // agg planes + re-zero agg for next layer
        act_conv_kernel<<<(N * 64 + 255) / 256, 256>>>(agg, agg_h, agg_l, N * 64);

        // hidden_n = relu([h_n | agg | ext_n] @ Wn1 + bn1) -> planes
        launch_tgemm(make_segs(3,
                         hn_h, hn_l, nullptr, 256,
                         agg_h, agg_l, nullptr, 256,
                         extn_h, extn_l, nullptr, 64),
                     Wn1th, Wn1tl, 576, noG, bn1l, nullptr, hidn_h, hidn_l,
                     N, 256, 1, 0);

        // h_n += hidden_n @ Wn2 + bn2 (residual, fp32) + planes
        launch_tgemm(make_segs(1, hidn_h, hidn_l, nullptr, 256),
                     Wn2th, Wn2tl, 256, noG, bn2l, hn, hn_h, hn_l, N, 256, 0, 1);
    }

    // --- decode ---
    // R = hn @ Wd1[128:384]  (node space; pair@W1 = R[src] + R[dst] by linearity)
    {
        SegList sr = make_segs(1, hn_h, hn_l, nullptr, 256);
        sr.s[0].boff = 128;
        launch_tgemm(sr, Wd1t_h, Wd1t_l, 384, noG, nullptr, R, nullptr, nullptr,
                     N, 128, 0, 0);
    }
    sym_kernel<<<(int)(((size_t)nh * 128 + 255) / 256), 256>>>(he, symh, syml, nh);

    // dec1 = relu(sym@Wd1[0:128] + R[src] + R[dst] + bd1) -> planes
    launch_tgemm(make_segs(1, symh, syml, nullptr, 128),
                 Wd1t_h, Wd1t_l, 384,
                 make_gadd(R, src, 128, 0, R, dst, 128, 0),
                 bd1, nullptr, dec1_h, dec1_l, nh, 128, 1, 0);

    // out = relu(dec1 @ Wd2 + bd2) @ Wd3 + bd3   (fused final projection)
    launch_tgemm(make_segs(1, dec1_h, dec1_l, nullptr, 128),
                 Wd2t_h, Wd2t_l, 128, noG, bd2, nullptr, nullptr, nullptr,
                 nh, 128, 1, 0, nullptr, Wd3, bd3, (float*)d_out);
}